// round 5
// baseline (speedup 1.0000x reference)
#include <cuda_runtime.h>
#include <math.h>

#define D        1024
#define E_TOT    10
#define E_TRUE   8
#define MAX_T    8192
#define BM       128
#define BN       128
#define BK       16

// Routing scratch (device globals: the sanctioned scratch space)
__device__ int   g_cnt[E_TRUE];
__device__ int   g_tok[E_TRUE * MAX_T];
__device__ float g_wt [E_TRUE * MAX_T];

// ---- packed f32x2 helpers (Blackwell; ptxas never emits these from C++) ----
__device__ __forceinline__ unsigned long long pack2(float a, float b) {
    unsigned long long r;
    asm("mov.b64 %0, {%1, %2};" : "=l"(r) : "f"(a), "f"(b));
    return r;
}
__device__ __forceinline__ void unpack2(unsigned long long v, float& a, float& b) {
    asm("mov.b64 {%0, %1}, %2;" : "=f"(a), "=f"(b) : "l"(v));
}
__device__ __forceinline__ void fma2(unsigned long long& d,
                                     unsigned long long a,
                                     unsigned long long b) {
    asm("fma.rn.f32x2 %0, %1, %2, %0;" : "+l"(d) : "l"(a), "l"(b));
}

// ---------------------------------------------------------------------------
__global__ void init_kernel() {
    if (threadIdx.x < E_TRUE) g_cnt[threadIdx.x] = 0;
}

// One warp per token: 10 dot products (len 1024), softmax, top-2, null-mask,
// renormalize, scatter into per-expert lists.
__global__ void gate_kernel(const float* __restrict__ x,
                            const float* __restrict__ gw,
                            const float* __restrict__ gb, int T) {
    int gtid = blockIdx.x * blockDim.x + threadIdx.x;
    int t = gtid >> 5;
    int lane = gtid & 31;
    if (t >= T) return;
    const float* xr = x + (size_t)t * D;

    float dot[E_TOT];
#pragma unroll
    for (int e = 0; e < E_TOT; e++) dot[e] = 0.f;

    for (int i = lane; i < D; i += 32) {
        float xv = xr[i];
#pragma unroll
        for (int e = 0; e < E_TOT; e++) dot[e] += xv * gw[e * D + i];
    }
#pragma unroll
    for (int e = 0; e < E_TOT; e++) {
#pragma unroll
        for (int off = 16; off; off >>= 1)
            dot[e] += __shfl_xor_sync(0xffffffffu, dot[e], off);
    }
    if (lane == 0) {
        float p[E_TOT];
        float mx = -1e30f;
#pragma unroll
        for (int e = 0; e < E_TOT; e++) {
            p[e] = dot[e] + gb[e];
            mx = fmaxf(mx, p[e]);
        }
        float s = 0.f;
#pragma unroll
        for (int e = 0; e < E_TOT; e++) { p[e] = expf(p[e] - mx); s += p[e]; }
        // top-2, lowest index wins ties (matches lax.top_k)
        int i1 = 0;
#pragma unroll
        for (int e = 1; e < E_TOT; e++) if (p[e] > p[i1]) i1 = e;
        int i2 = (i1 == 0) ? 1 : 0;
#pragma unroll
        for (int e = 0; e < E_TOT; e++)
            if (e != i1 && p[e] > p[i2]) i2 = e;

        float w1 = p[i1] / s, w2 = p[i2] / s;
        float t1 = (i1 < E_TRUE) ? w1 : 0.f;
        float t2 = (i2 < E_TRUE) ? w2 : 0.f;
        float den = t1 + t2;
        den = (den > 0.f) ? den : 1.f;
        t1 /= den;
        t2 /= den;
        if (i1 < E_TRUE) {
            int pos = atomicAdd(&g_cnt[i1], 1);
            g_tok[i1 * MAX_T + pos] = t;
            g_wt [i1 * MAX_T + pos] = t1;
        }
        if (i2 < E_TRUE) {
            int pos = atomicAdd(&g_cnt[i2], 1);
            g_tok[i2 * MAX_T + pos] = t;
            g_wt [i2 * MAX_T + pos] = t2;
        }
    }
}

// Grouped gather-GEMM: grid (N-tiles, M-tiles, experts). Double-buffered
// 128x128x16 tile, 8x8 per-thread micro-tile computed as 4 m-pairs x 8 n
// with packed fma.rn.f32x2. Epilogue: out[token] += w * (y + bias) via
// atomicAdd (<=2 adds/element -> commutative -> deterministic).
__global__ __launch_bounds__(256)
void moe_gemm(const float* __restrict__ x,
              const float* __restrict__ ew,
              const float* __restrict__ eb,
              float* __restrict__ out) {
    const int e = blockIdx.z;
    const int rows = g_cnt[e];
    const int m0 = blockIdx.y * BM;
    if (m0 >= rows) return;
    const int n0 = blockIdx.x * BN;

    __shared__ float As[2][BK][BM];
    __shared__ float Bs[2][BK][BN];
    __shared__ int   sTok[BM];
    __shared__ float sW[BM];

    const int tid = threadIdx.x;
    if (tid < BM) {
        int gr = m0 + tid;
        if (gr < rows) {
            sTok[tid] = g_tok[e * MAX_T + gr];
            sW[tid]   = g_wt [e * MAX_T + gr];
        } else {
            sTok[tid] = 0;   // valid address, result discarded in epilogue
            sW[tid]   = 0.f;
        }
    }
    __syncthreads();

    const float* wbase = ew + (size_t)e * D * D + n0;

    int aRow[2], aCol[2], bRow[2], bCol[2];
#pragma unroll
    for (int j = 0; j < 2; j++) {
        int idx = tid * 2 + j;          // 0..511
        aRow[j] = idx >> 2;  aCol[j] = idx & 3;   // 128 rows x 4 float4
        bRow[j] = idx >> 5;  bCol[j] = idx & 31;  // 16 rows  x 32 float4
    }
    float4 aReg[2], bReg[2];

    auto ldgAB = [&](int k0) {
#pragma unroll
        for (int j = 0; j < 2; j++) {
            aReg[j] = *(const float4*)(x + (size_t)sTok[aRow[j]] * D + k0 + aCol[j] * 4);
            bReg[j] = *(const float4*)(wbase + (size_t)(k0 + bRow[j]) * D + bCol[j] * 4);
        }
    };
    auto stsAB = [&](int buf) {
#pragma unroll
        for (int j = 0; j < 2; j++) {
            As[buf][aCol[j] * 4 + 0][aRow[j]] = aReg[j].x;
            As[buf][aCol[j] * 4 + 1][aRow[j]] = aReg[j].y;
            As[buf][aCol[j] * 4 + 2][aRow[j]] = aReg[j].z;
            As[buf][aCol[j] * 4 + 3][aRow[j]] = aReg[j].w;
            *(float4*)&Bs[buf][bRow[j]][bCol[j] * 4] = bReg[j];
        }
    };

    ldgAB(0);
    stsAB(0);
    __syncthreads();

    unsigned long long acc[4][8];
#pragma unroll
    for (int i = 0; i < 4; i++)
#pragma unroll
        for (int j = 0; j < 8; j++) acc[i][j] = 0ull;

    const int tmBase = (tid >> 4) * 8;
    const int tnBase = (tid & 15) * 8;
    const int NKB = D / BK;

    for (int kb = 0; kb < NKB; kb++) {
        const int buf = kb & 1;
        if (kb + 1 < NKB) ldgAB((kb + 1) * BK);
#pragma unroll
        for (int k = 0; k < BK; k++) {
            unsigned long long a2[4];
            const unsigned long long* ap =
                (const unsigned long long*)&As[buf][k][tmBase];
            a2[0] = ap[0]; a2[1] = ap[1]; a2[2] = ap[2]; a2[3] = ap[3];
            float bv[8];
            *(float4*)&bv[0] = *(const float4*)&Bs[buf][k][tnBase];
            *(float4*)&bv[4] = *(const float4*)&Bs[buf][k][tnBase + 4];
#pragma unroll
            for (int j = 0; j < 8; j++) {
                unsigned long long b2 = pack2(bv[j], bv[j]);
#pragma unroll
                for (int i = 0; i < 4; i++) fma2(acc[i][j], a2[i], b2);
            }
        }
        if (kb + 1 < NKB) stsAB(buf ^ 1);
        __syncthreads();
    }

    // Epilogue
    float bias[8];
#pragma unroll
    for (int j = 0; j < 8; j++) bias[j] = eb[e * D + n0 + tnBase + j];

#pragma unroll
    for (int i = 0; i < 4; i++) {
#pragma unroll
        for (int p = 0; p < 2; p++) {
            int ml = tmBase + 2 * i + p;
            int gr = m0 + ml;
            if (gr < rows) {
                int tok = sTok[ml];
                float w = sW[ml];
                float* orow = out + (size_t)tok * D + n0 + tnBase;
#pragma unroll
                for (int j = 0; j < 8; j++) {
                    float lo, hi;
                    unpack2(acc[i][j], lo, hi);
                    float y = p ? hi : lo;
                    atomicAdd(&orow[j], w * (y + bias[j]));
                }
            }
        }
    }
}

// ---------------------------------------------------------------------------
extern "C" void kernel_launch(void* const* d_in, const int* in_sizes, int n_in,
                              void* d_out, int out_size) {
    const float* x  = (const float*)d_in[0];
    const float* gw = (const float*)d_in[1];
    const float* gb = (const float*)d_in[2];
    const float* ew = (const float*)d_in[3];
    const float* eb = (const float*)d_in[4];
    float* out = (float*)d_out;

    const int T = in_sizes[0] / D;

    cudaMemsetAsync(out, 0, (size_t)out_size * sizeof(float), 0);
    init_kernel<<<1, 32>>>();

    int threads = 256;
    int blocks = (T * 32 + threads - 1) / threads;
    gate_kernel<<<blocks, threads>>>(x, gw, gb, T);

    dim3 grid(D / BN, (T + BM - 1) / BM, E_TRUE);
    moe_gemm<<<grid, 256>>>(x, ew, eb, out);
}

// round 6
// speedup vs baseline: 1.0010x; 1.0010x over previous
#include <cuda_runtime.h>
#include <math.h>

#define D        1024
#define E_TOT    10
#define E_TRUE   8
#define MAX_T    8192
#define BM       128
#define BN       128
#define BK       16

// Routing scratch (device globals: the sanctioned scratch space)
__device__ int   g_cnt[E_TRUE];
__device__ int   g_tok[E_TRUE * MAX_T];
__device__ float g_wt [E_TRUE * MAX_T];

// ---- packed f32x2 helpers (Blackwell; ptxas never emits these from C++) ----
__device__ __forceinline__ unsigned long long pack2(float a, float b) {
    unsigned long long r;
    asm("mov.b64 %0, {%1, %2};" : "=l"(r) : "f"(a), "f"(b));
    return r;
}
__device__ __forceinline__ void unpack2(unsigned long long v, float& a, float& b) {
    asm("mov.b64 {%0, %1}, %2;" : "=f"(a), "=f"(b) : "l"(v));
}
__device__ __forceinline__ void fma2(unsigned long long& d,
                                     unsigned long long a,
                                     unsigned long long b) {
    asm("fma.rn.f32x2 %0, %1, %2, %0;" : "+l"(d) : "l"(a), "l"(b));
}

// ---------------------------------------------------------------------------
__global__ void init_kernel() {
    if (threadIdx.x < E_TRUE) g_cnt[threadIdx.x] = 0;
}

// One warp per token: 10 dot products (len 1024), softmax, top-2, null-mask,
// renormalize, scatter into per-expert lists.
__global__ void gate_kernel(const float* __restrict__ x,
                            const float* __restrict__ gw,
                            const float* __restrict__ gb, int T) {
    int gtid = blockIdx.x * blockDim.x + threadIdx.x;
    int t = gtid >> 5;
    int lane = gtid & 31;
    if (t >= T) return;
    const float* xr = x + (size_t)t * D;

    float dot[E_TOT];
#pragma unroll
    for (int e = 0; e < E_TOT; e++) dot[e] = 0.f;

    for (int i = lane; i < D; i += 32) {
        float xv = xr[i];
#pragma unroll
        for (int e = 0; e < E_TOT; e++) dot[e] += xv * gw[e * D + i];
    }
#pragma unroll
    for (int e = 0; e < E_TOT; e++) {
#pragma unroll
        for (int off = 16; off; off >>= 1)
            dot[e] += __shfl_xor_sync(0xffffffffu, dot[e], off);
    }
    if (lane == 0) {
        float p[E_TOT];
        float mx = -1e30f;
#pragma unroll
        for (int e = 0; e < E_TOT; e++) {
            p[e] = dot[e] + gb[e];
            mx = fmaxf(mx, p[e]);
        }
        float s = 0.f;
#pragma unroll
        for (int e = 0; e < E_TOT; e++) { p[e] = expf(p[e] - mx); s += p[e]; }
        // top-2, lowest index wins ties (matches lax.top_k)
        int i1 = 0;
#pragma unroll
        for (int e = 1; e < E_TOT; e++) if (p[e] > p[i1]) i1 = e;
        int i2 = (i1 == 0) ? 1 : 0;
#pragma unroll
        for (int e = 0; e < E_TOT; e++)
            if (e != i1 && p[e] > p[i2]) i2 = e;

        float w1 = p[i1] / s, w2 = p[i2] / s;
        float t1 = (i1 < E_TRUE) ? w1 : 0.f;
        float t2 = (i2 < E_TRUE) ? w2 : 0.f;
        float den = t1 + t2;
        den = (den > 0.f) ? den : 1.f;
        t1 /= den;
        t2 /= den;
        if (i1 < E_TRUE) {
            int pos = atomicAdd(&g_cnt[i1], 1);
            g_tok[i1 * MAX_T + pos] = t;
            g_wt [i1 * MAX_T + pos] = t1;
        }
        if (i2 < E_TRUE) {
            int pos = atomicAdd(&g_cnt[i2], 1);
            g_tok[i2 * MAX_T + pos] = t;
            g_wt [i2 * MAX_T + pos] = t2;
        }
    }
}

// Grouped gather-GEMM: grid (N-tiles, M-tiles, experts). Double-buffered
// 128x128x16 tile, 8x8 per-thread micro-tile computed as 4 m-pairs x 8 n
// with packed fma.rn.f32x2. Epilogue: out[token] += w * (y + bias) via
// atomicAdd (<=2 adds/element -> commutative -> deterministic).
__global__ __launch_bounds__(256)
void moe_gemm(const float* __restrict__ x,
              const float* __restrict__ ew,
              const float* __restrict__ eb,
              float* __restrict__ out) {
    const int e = blockIdx.z;
    const int rows = g_cnt[e];
    const int m0 = blockIdx.y * BM;
    if (m0 >= rows) return;
    const int n0 = blockIdx.x * BN;

    __shared__ float As[2][BK][BM];
    __shared__ float Bs[2][BK][BN];
    __shared__ int   sTok[BM];
    __shared__ float sW[BM];

    const int tid = threadIdx.x;
    if (tid < BM) {
        int gr = m0 + tid;
        if (gr < rows) {
            sTok[tid] = g_tok[e * MAX_T + gr];
            sW[tid]   = g_wt [e * MAX_T + gr];
        } else {
            sTok[tid] = 0;   // valid address, result discarded in epilogue
            sW[tid]   = 0.f;
        }
    }
    __syncthreads();

    const float* wbase = ew + (size_t)e * D * D + n0;

    int aRow[2], aCol[2], bRow[2], bCol[2];
#pragma unroll
    for (int j = 0; j < 2; j++) {
        int idx = tid * 2 + j;          // 0..511
        aRow[j] = idx >> 2;  aCol[j] = idx & 3;   // 128 rows x 4 float4
        bRow[j] = idx >> 5;  bCol[j] = idx & 31;  // 16 rows  x 32 float4
    }
    float4 aReg[2], bReg[2];

    auto ldgAB = [&](int k0) {
#pragma unroll
        for (int j = 0; j < 2; j++) {
            aReg[j] = *(const float4*)(x + (size_t)sTok[aRow[j]] * D + k0 + aCol[j] * 4);
            bReg[j] = *(const float4*)(wbase + (size_t)(k0 + bRow[j]) * D + bCol[j] * 4);
        }
    };
    auto stsAB = [&](int buf) {
#pragma unroll
        for (int j = 0; j < 2; j++) {
            As[buf][aCol[j] * 4 + 0][aRow[j]] = aReg[j].x;
            As[buf][aCol[j] * 4 + 1][aRow[j]] = aReg[j].y;
            As[buf][aCol[j] * 4 + 2][aRow[j]] = aReg[j].z;
            As[buf][aCol[j] * 4 + 3][aRow[j]] = aReg[j].w;
            *(float4*)&Bs[buf][bRow[j]][bCol[j] * 4] = bReg[j];
        }
    };

    ldgAB(0);
    stsAB(0);
    __syncthreads();

    unsigned long long acc[4][8];
#pragma unroll
    for (int i = 0; i < 4; i++)
#pragma unroll
        for (int j = 0; j < 8; j++) acc[i][j] = 0ull;

    const int tmBase = (tid >> 4) * 8;
    const int tnBase = (tid & 15) * 8;
    const int NKB = D / BK;

    for (int kb = 0; kb < NKB; kb++) {
        const int buf = kb & 1;
        if (kb + 1 < NKB) ldgAB((kb + 1) * BK);
#pragma unroll
        for (int k = 0; k < BK; k++) {
            unsigned long long a2[4];
            const unsigned long long* ap =
                (const unsigned long long*)&As[buf][k][tmBase];
            a2[0] = ap[0]; a2[1] = ap[1]; a2[2] = ap[2]; a2[3] = ap[3];
            float bv[8];
            *(float4*)&bv[0] = *(const float4*)&Bs[buf][k][tnBase];
            *(float4*)&bv[4] = *(const float4*)&Bs[buf][k][tnBase + 4];
#pragma unroll
            for (int j = 0; j < 8; j++) {
                unsigned long long b2 = pack2(bv[j], bv[j]);
#pragma unroll
                for (int i = 0; i < 4; i++) fma2(acc[i][j], a2[i], b2);
            }
        }
        if (kb + 1 < NKB) stsAB(buf ^ 1);
        __syncthreads();
    }

    // Epilogue
    float bias[8];
#pragma unroll
    for (int j = 0; j < 8; j++) bias[j] = eb[e * D + n0 + tnBase + j];

#pragma unroll
    for (int i = 0; i < 4; i++) {
#pragma unroll
        for (int p = 0; p < 2; p++) {
            int ml = tmBase + 2 * i + p;
            int gr = m0 + ml;
            if (gr < rows) {
                int tok = sTok[ml];
                float w = sW[ml];
                float* orow = out + (size_t)tok * D + n0 + tnBase;
#pragma unroll
                for (int j = 0; j < 8; j++) {
                    float lo, hi;
                    unpack2(acc[i][j], lo, hi);
                    float y = p ? hi : lo;
                    atomicAdd(&orow[j], w * (y + bias[j]));
                }
            }
        }
    }
}

// ---------------------------------------------------------------------------
extern "C" void kernel_launch(void* const* d_in, const int* in_sizes, int n_in,
                              void* d_out, int out_size) {
    const float* x  = (const float*)d_in[0];
    const float* gw = (const float*)d_in[1];
    const float* gb = (const float*)d_in[2];
    const float* ew = (const float*)d_in[3];
    const float* eb = (const float*)d_in[4];
    float* out = (float*)d_out;

    const int T = in_sizes[0] / D;

    cudaMemsetAsync(out, 0, (size_t)out_size * sizeof(float), 0);
    init_kernel<<<1, 32>>>();

    int threads = 256;
    int blocks = (T * 32 + threads - 1) / threads;
    gate_kernel<<<blocks, threads>>>(x, gw, gb, T);

    dim3 grid(D / BN, (T + BM - 1) / BM, E_TRUE);
    moe_gemm<<<grid, 256>>>(x, ew, eb, out);
}

// round 7
// speedup vs baseline: 1.0012x; 1.0002x over previous
#include <cuda_runtime.h>
#include <math.h>

#define D        1024
#define E_TOT    10
#define E_TRUE   8
#define MAX_T    8192
#define BM       128
#define BN       128
#define BK       16

// Routing scratch (device globals: the sanctioned scratch space)
__device__ int   g_cnt[E_TRUE];
__device__ int   g_tok[E_TRUE * MAX_T];
__device__ float g_wt [E_TRUE * MAX_T];

// ---- packed f32x2 helpers (Blackwell; ptxas never emits these from C++) ----
__device__ __forceinline__ unsigned long long pack2(float a, float b) {
    unsigned long long r;
    asm("mov.b64 %0, {%1, %2};" : "=l"(r) : "f"(a), "f"(b));
    return r;
}
__device__ __forceinline__ void unpack2(unsigned long long v, float& a, float& b) {
    asm("mov.b64 {%0, %1}, %2;" : "=f"(a), "=f"(b) : "l"(v));
}
__device__ __forceinline__ void fma2(unsigned long long& d,
                                     unsigned long long a,
                                     unsigned long long b) {
    asm("fma.rn.f32x2 %0, %1, %2, %0;" : "+l"(d) : "l"(a), "l"(b));
}

// ---------------------------------------------------------------------------
__global__ void init_kernel() {
    if (threadIdx.x < E_TRUE) g_cnt[threadIdx.x] = 0;
}

// One warp per token: 10 dot products (len 1024), softmax, top-2, null-mask,
// renormalize, scatter into per-expert lists.
__global__ void gate_kernel(const float* __restrict__ x,
                            const float* __restrict__ gw,
                            const float* __restrict__ gb, int T) {
    int gtid = blockIdx.x * blockDim.x + threadIdx.x;
    int t = gtid >> 5;
    int lane = gtid & 31;
    if (t >= T) return;
    const float* xr = x + (size_t)t * D;

    float dot[E_TOT];
#pragma unroll
    for (int e = 0; e < E_TOT; e++) dot[e] = 0.f;

    for (int i = lane; i < D; i += 32) {
        float xv = xr[i];
#pragma unroll
        for (int e = 0; e < E_TOT; e++) dot[e] += xv * gw[e * D + i];
    }
#pragma unroll
    for (int e = 0; e < E_TOT; e++) {
#pragma unroll
        for (int off = 16; off; off >>= 1)
            dot[e] += __shfl_xor_sync(0xffffffffu, dot[e], off);
    }
    if (lane == 0) {
        float p[E_TOT];
        float mx = -1e30f;
#pragma unroll
        for (int e = 0; e < E_TOT; e++) {
            p[e] = dot[e] + gb[e];
            mx = fmaxf(mx, p[e]);
        }
        float s = 0.f;
#pragma unroll
        for (int e = 0; e < E_TOT; e++) { p[e] = expf(p[e] - mx); s += p[e]; }
        // top-2, lowest index wins ties (matches lax.top_k)
        int i1 = 0;
#pragma unroll
        for (int e = 1; e < E_TOT; e++) if (p[e] > p[i1]) i1 = e;
        int i2 = (i1 == 0) ? 1 : 0;
#pragma unroll
        for (int e = 0; e < E_TOT; e++)
            if (e != i1 && p[e] > p[i2]) i2 = e;

        float w1 = p[i1] / s, w2 = p[i2] / s;
        float t1 = (i1 < E_TRUE) ? w1 : 0.f;
        float t2 = (i2 < E_TRUE) ? w2 : 0.f;
        float den = t1 + t2;
        den = (den > 0.f) ? den : 1.f;
        t1 /= den;
        t2 /= den;
        if (i1 < E_TRUE) {
            int pos = atomicAdd(&g_cnt[i1], 1);
            g_tok[i1 * MAX_T + pos] = t;
            g_wt [i1 * MAX_T + pos] = t1;
        }
        if (i2 < E_TRUE) {
            int pos = atomicAdd(&g_cnt[i2], 1);
            g_tok[i2 * MAX_T + pos] = t;
            g_wt [i2 * MAX_T + pos] = t2;
        }
    }
}

// Grouped gather-GEMM: grid (N-tiles, M-tiles, experts). Double-buffered
// 128x128x16 tile, 8x8 per-thread micro-tile computed as 4 m-pairs x 8 n
// with packed fma.rn.f32x2. Epilogue: out[token] += w * (y + bias) via
// atomicAdd (<=2 adds/element -> commutative -> deterministic).
__global__ __launch_bounds__(256)
void moe_gemm(const float* __restrict__ x,
              const float* __restrict__ ew,
              const float* __restrict__ eb,
              float* __restrict__ out) {
    const int e = blockIdx.z;
    const int rows = g_cnt[e];
    const int m0 = blockIdx.y * BM;
    if (m0 >= rows) return;
    const int n0 = blockIdx.x * BN;

    __shared__ float As[2][BK][BM];
    __shared__ float Bs[2][BK][BN];
    __shared__ int   sTok[BM];
    __shared__ float sW[BM];

    const int tid = threadIdx.x;
    if (tid < BM) {
        int gr = m0 + tid;
        if (gr < rows) {
            sTok[tid] = g_tok[e * MAX_T + gr];
            sW[tid]   = g_wt [e * MAX_T + gr];
        } else {
            sTok[tid] = 0;   // valid address, result discarded in epilogue
            sW[tid]   = 0.f;
        }
    }
    __syncthreads();

    const float* wbase = ew + (size_t)e * D * D + n0;

    int aRow[2], aCol[2], bRow[2], bCol[2];
#pragma unroll
    for (int j = 0; j < 2; j++) {
        int idx = tid * 2 + j;          // 0..511
        aRow[j] = idx >> 2;  aCol[j] = idx & 3;   // 128 rows x 4 float4
        bRow[j] = idx >> 5;  bCol[j] = idx & 31;  // 16 rows  x 32 float4
    }
    float4 aReg[2], bReg[2];

    auto ldgAB = [&](int k0) {
#pragma unroll
        for (int j = 0; j < 2; j++) {
            aReg[j] = *(const float4*)(x + (size_t)sTok[aRow[j]] * D + k0 + aCol[j] * 4);
            bReg[j] = *(const float4*)(wbase + (size_t)(k0 + bRow[j]) * D + bCol[j] * 4);
        }
    };
    auto stsAB = [&](int buf) {
#pragma unroll
        for (int j = 0; j < 2; j++) {
            As[buf][aCol[j] * 4 + 0][aRow[j]] = aReg[j].x;
            As[buf][aCol[j] * 4 + 1][aRow[j]] = aReg[j].y;
            As[buf][aCol[j] * 4 + 2][aRow[j]] = aReg[j].z;
            As[buf][aCol[j] * 4 + 3][aRow[j]] = aReg[j].w;
            *(float4*)&Bs[buf][bRow[j]][bCol[j] * 4] = bReg[j];
        }
    };

    ldgAB(0);
    stsAB(0);
    __syncthreads();

    unsigned long long acc[4][8];
#pragma unroll
    for (int i = 0; i < 4; i++)
#pragma unroll
        for (int j = 0; j < 8; j++) acc[i][j] = 0ull;

    const int tmBase = (tid >> 4) * 8;
    const int tnBase = (tid & 15) * 8;
    const int NKB = D / BK;

    for (int kb = 0; kb < NKB; kb++) {
        const int buf = kb & 1;
        if (kb + 1 < NKB) ldgAB((kb + 1) * BK);
#pragma unroll
        for (int k = 0; k < BK; k++) {
            unsigned long long a2[4];
            const unsigned long long* ap =
                (const unsigned long long*)&As[buf][k][tmBase];
            a2[0] = ap[0]; a2[1] = ap[1]; a2[2] = ap[2]; a2[3] = ap[3];
            float bv[8];
            *(float4*)&bv[0] = *(const float4*)&Bs[buf][k][tnBase];
            *(float4*)&bv[4] = *(const float4*)&Bs[buf][k][tnBase + 4];
#pragma unroll
            for (int j = 0; j < 8; j++) {
                unsigned long long b2 = pack2(bv[j], bv[j]);
#pragma unroll
                for (int i = 0; i < 4; i++) fma2(acc[i][j], a2[i], b2);
            }
        }
        if (kb + 1 < NKB) stsAB(buf ^ 1);
        __syncthreads();
    }

    // Epilogue
    float bias[8];
#pragma unroll
    for (int j = 0; j < 8; j++) bias[j] = eb[e * D + n0 + tnBase + j];

#pragma unroll
    for (int i = 0; i < 4; i++) {
#pragma unroll
        for (int p = 0; p < 2; p++) {
            int ml = tmBase + 2 * i + p;
            int gr = m0 + ml;
            if (gr < rows) {
                int tok = sTok[ml];
                float w = sW[ml];
                float* orow = out + (size_t)tok * D + n0 + tnBase;
#pragma unroll
                for (int j = 0; j < 8; j++) {
                    float lo, hi;
                    unpack2(acc[i][j], lo, hi);
                    float y = p ? hi : lo;
                    atomicAdd(&orow[j], w * (y + bias[j]));
                }
            }
        }
    }
}

// ---------------------------------------------------------------------------
extern "C" void kernel_launch(void* const* d_in, const int* in_sizes, int n_in,
                              void* d_out, int out_size) {
    const float* x  = (const float*)d_in[0];
    const float* gw = (const float*)d_in[1];
    const float* gb = (const float*)d_in[2];
    const float* ew = (const float*)d_in[3];
    const float* eb = (const float*)d_in[4];
    float* out = (float*)d_out;

    const int T = in_sizes[0] / D;

    cudaMemsetAsync(out, 0, (size_t)out_size * sizeof(float), 0);
    init_kernel<<<1, 32>>>();

    int threads = 256;
    int blocks = (T * 32 + threads - 1) / threads;
    gate_kernel<<<blocks, threads>>>(x, gw, gb, T);

    dim3 grid(D / BN, (T + BM - 1) / BM, E_TRUE);
    moe_gemm<<<grid, 256>>>(x, ew, eb, out);
}

// round 9
// speedup vs baseline: 1.9495x; 1.9471x over previous
#include <cuda_runtime.h>
#include <cuda_bf16.h>
#include <math.h>
#include <stdint.h>

#define D        1024
#define E_TOT    10
#define E_TRUE   8
#define MAX_T    8192
#define BM       128
#define BN       128
#define KT       64        // k-chunk: 64 bf16 = 128 bytes = one SW128 row
#define NKC      (D / KT)  // 16 chunks

// ---------------- device scratch (__device__ globals) ----------------------
__device__ int   g_cnt[E_TRUE];
__device__ int   g_tok[E_TRUE * MAX_T];
__device__ float g_wt [E_TRUE * MAX_T];
__device__ __nv_bfloat16 g_xhi[MAX_T * D];
__device__ __nv_bfloat16 g_xlo[MAX_T * D];
__device__ __nv_bfloat16 g_whi[E_TRUE * D * D];   // [e][n][k] (transposed)
__device__ __nv_bfloat16 g_wlo[E_TRUE * D * D];

// ---------------- PTX helpers (all <= sm_90 baseline features) -------------
__device__ __forceinline__ uint32_t smem_u32(const void* p) {
    uint32_t a;
    asm("{ .reg .u64 t; cvta.to.shared.u64 t, %1; cvt.u32.u64 %0, t; }"
        : "=r"(a) : "l"(p));
    return a;
}
#define SW128(off) ((off) ^ (((off) >> 3) & 0x70))

__device__ __forceinline__ void cp16(uint32_t dst, const void* src) {
    asm volatile("cp.async.cg.shared.global [%0], [%1], 16;"
                 :: "r"(dst), "l"(__cvta_generic_to_global(src)));
}
__device__ __forceinline__ void cp_commit() {
    asm volatile("cp.async.commit_group;");
}
template <int N>
__device__ __forceinline__ void cp_wait() {
    asm volatile("cp.async.wait_group %0;" :: "n"(N));
}

__device__ __forceinline__ void ldsm_x4(uint32_t* r, uint32_t addr) {
    asm volatile("ldmatrix.sync.aligned.m8n8.x4.shared.b16 {%0,%1,%2,%3}, [%4];"
                 : "=r"(r[0]), "=r"(r[1]), "=r"(r[2]), "=r"(r[3]) : "r"(addr));
}
__device__ __forceinline__ void mma16816(float* d, const uint32_t* a,
                                         uint32_t b0, uint32_t b1) {
    asm volatile(
        "mma.sync.aligned.m16n8k16.row.col.f32.bf16.bf16.f32 "
        "{%0,%1,%2,%3}, {%4,%5,%6,%7}, {%8,%9}, {%0,%1,%2,%3};"
        : "+f"(d[0]), "+f"(d[1]), "+f"(d[2]), "+f"(d[3])
        : "r"(a[0]), "r"(a[1]), "r"(a[2]), "r"(a[3]), "r"(b0), "r"(b1));
}

// ---------------- SMEM layout ----------------------------------------------
#define OFF_TOK  0                  // 128 ints
#define OFF_W    512                // 128 floats
#define OFF_A    1024               // A(buf,half): 4 x 16KB
#define OFF_B    (1024 + 4*16384)   // B(buf,half): 4 x 16KB
#define SMEM_BYTES (OFF_B + 4*16384)

// ---------------------------------------------------------------------------
__global__ void init_kernel() {
    if (threadIdx.x < E_TRUE) g_cnt[threadIdx.x] = 0;
}

// One warp per token: gating, softmax, top-2, null-mask, renorm, scatter.
__global__ void gate_kernel(const float* __restrict__ x,
                            const float* __restrict__ gw,
                            const float* __restrict__ gb, int T) {
    int gtid = blockIdx.x * blockDim.x + threadIdx.x;
    int t = gtid >> 5;
    int lane = gtid & 31;
    if (t >= T) return;
    const float* xr = x + (size_t)t * D;

    float dot[E_TOT];
#pragma unroll
    for (int e = 0; e < E_TOT; e++) dot[e] = 0.f;
    for (int i = lane; i < D; i += 32) {
        float xv = xr[i];
#pragma unroll
        for (int e = 0; e < E_TOT; e++) dot[e] += xv * gw[e * D + i];
    }
#pragma unroll
    for (int e = 0; e < E_TOT; e++) {
#pragma unroll
        for (int off = 16; off; off >>= 1)
            dot[e] += __shfl_xor_sync(0xffffffffu, dot[e], off);
    }
    if (lane == 0) {
        float p[E_TOT];
        float mx = -1e30f;
#pragma unroll
        for (int e = 0; e < E_TOT; e++) { p[e] = dot[e] + gb[e]; mx = fmaxf(mx, p[e]); }
        float s = 0.f;
#pragma unroll
        for (int e = 0; e < E_TOT; e++) { p[e] = expf(p[e] - mx); s += p[e]; }
        int i1 = 0;
#pragma unroll
        for (int e = 1; e < E_TOT; e++) if (p[e] > p[i1]) i1 = e;
        int i2 = (i1 == 0) ? 1 : 0;
#pragma unroll
        for (int e = 0; e < E_TOT; e++) if (e != i1 && p[e] > p[i2]) i2 = e;

        float w1 = p[i1] / s, w2 = p[i2] / s;
        float t1 = (i1 < E_TRUE) ? w1 : 0.f;
        float t2 = (i2 < E_TRUE) ? w2 : 0.f;
        float den = t1 + t2;
        den = (den > 0.f) ? den : 1.f;
        t1 /= den; t2 /= den;
        if (i1 < E_TRUE) {
            int pos = atomicAdd(&g_cnt[i1], 1);
            g_tok[i1 * MAX_T + pos] = t;  g_wt[i1 * MAX_T + pos] = t1;
        }
        if (i2 < E_TRUE) {
            int pos = atomicAdd(&g_cnt[i2], 1);
            g_tok[i2 * MAX_T + pos] = t;  g_wt[i2 * MAX_T + pos] = t2;
        }
    }
}

// x fp32 -> (hi, lo) bf16
__global__ void convert_x(const float* __restrict__ x, int n4) {
    int i = blockIdx.x * blockDim.x + threadIdx.x;
    if (i >= n4) return;
    float4 v = ((const float4*)x)[i];
    __nv_bfloat16 h0 = __float2bfloat16_rn(v.x);
    __nv_bfloat16 h1 = __float2bfloat16_rn(v.y);
    __nv_bfloat16 h2 = __float2bfloat16_rn(v.z);
    __nv_bfloat16 h3 = __float2bfloat16_rn(v.w);
    __nv_bfloat16 l0 = __float2bfloat16_rn(v.x - __bfloat162float(h0));
    __nv_bfloat16 l1 = __float2bfloat16_rn(v.y - __bfloat162float(h1));
    __nv_bfloat16 l2 = __float2bfloat16_rn(v.z - __bfloat162float(h2));
    __nv_bfloat16 l3 = __float2bfloat16_rn(v.w - __bfloat162float(h3));
    __nv_bfloat162* ph = (__nv_bfloat162*)g_xhi;
    __nv_bfloat162* pl = (__nv_bfloat162*)g_xlo;
    ph[2*i]   = __nv_bfloat162(h0, h1);
    ph[2*i+1] = __nv_bfloat162(h2, h3);
    pl[2*i]   = __nv_bfloat162(l0, l1);
    pl[2*i+1] = __nv_bfloat162(l2, l3);
}

// ew[e][k][n] fp32 -> transposed (hi, lo) bf16 [e][n][k]
__global__ void convert_w(const float* __restrict__ ew) {
    __shared__ float tile[32][33];
    int e  = blockIdx.z;
    int n0 = blockIdx.x * 32;
    int k0 = blockIdx.y * 32;
    int tx = threadIdx.x, ty = threadIdx.y;
    tile[ty][tx] = ew[(size_t)e * D * D + (size_t)(k0 + ty) * D + n0 + tx];
    __syncthreads();
    float v = tile[tx][ty];
    __nv_bfloat16 hi = __float2bfloat16_rn(v);
    __nv_bfloat16 lo = __float2bfloat16_rn(v - __bfloat162float(hi));
    size_t o = (size_t)e * D * D + (size_t)(n0 + ty) * D + k0 + tx;
    g_whi[o] = hi;
    g_wlo[o] = lo;
}

// ---------------------------------------------------------------------------
// Grouped bf16-split HMMA GEMM. grid = (N/BN, maxMtiles, E_TRUE), 256 thr.
// Warp tile 64x32 (warp grid 2m x 4n), mma.sync.m16n8k16, 3 split passes.
__global__ __launch_bounds__(256, 1)
void moe_mma(const float* __restrict__ eb, float* __restrict__ out) {
    extern __shared__ __align__(1024) char smem[];
    const int e = blockIdx.z;
    const int rows = g_cnt[e];
    const int m0 = blockIdx.y * BM;
    if (m0 >= rows) return;
    const int n0 = blockIdx.x * BN;

    const uint32_t sb = smem_u32(smem);
    const int tid = threadIdx.x;
    const int wid = tid >> 5;
    const int lane = tid & 31;
    const int wm = (wid >> 2) * 64;     // warp m offset in tile
    const int wn = (wid & 3) * 32;      // warp n offset in tile

    int*   sTok = (int*)(smem + OFF_TOK);
    float* sW   = (float*)(smem + OFF_W);
    if (tid < BM) {
        int gr = m0 + tid;
        sTok[tid] = (gr < rows) ? g_tok[e * MAX_T + gr] : 0;
        sW[tid]   = (gr < rows) ? g_wt [e * MAX_T + gr] : 0.f;
    }
    __syncthreads();

    const __nv_bfloat16* xsrc[2] = { g_xhi, g_xlo };
    const __nv_bfloat16* wsrc[2] = { g_whi + (size_t)e * D * D,
                                     g_wlo + (size_t)e * D * D };

    // per-thread cp.async coordinates (4 groups of 256 threads -> 1024 rows*grp)
    int cRow[4], cGrp[4];
    uint32_t cSw[4];
#pragma unroll
    for (int t = 0; t < 4; t++) {
        int c = tid + t * 256;
        cRow[t] = c >> 3;
        cGrp[t] = c & 7;
        cSw[t]  = SW128((uint32_t)(cRow[t] * 128 + cGrp[t] * 16));
    }

    auto loadChunk = [&](int kc, int buf) {
        const int k0 = kc * KT;
#pragma unroll
        for (int half = 0; half < 2; half++) {
            uint32_t abase = sb + OFF_A + (buf * 2 + half) * 16384;
            uint32_t bbase = sb + OFF_B + (buf * 2 + half) * 16384;
#pragma unroll
            for (int t = 0; t < 4; t++) {
                cp16(abase + cSw[t],
                     xsrc[half] + (size_t)sTok[cRow[t]] * D + k0 + cGrp[t] * 8);
                cp16(bbase + cSw[t],
                     wsrc[half] + (size_t)(n0 + cRow[t]) * D + k0 + cGrp[t] * 8);
            }
        }
        cp_commit();
    };

    // ldmatrix per-lane pre-swizzle offsets (k-invariant part)
    uint32_t aOff[4], bOff[2];
#pragma unroll
    for (int i = 0; i < 4; i++)
        aOff[i] = (uint32_t)((wm + 16 * i + (lane & 15)) * 128 + (lane >> 4) * 16);
#pragma unroll
    for (int jj = 0; jj < 2; jj++)
        bOff[jj] = (uint32_t)((wn + 16 * jj + ((lane >> 3) & 1) * 8 + (lane & 7)) * 128
                              + (lane >> 4) * 16);

    float acc[4][4][4];
#pragma unroll
    for (int i = 0; i < 4; i++)
#pragma unroll
        for (int j = 0; j < 4; j++)
#pragma unroll
            for (int r = 0; r < 4; r++) acc[i][j][r] = 0.f;

    loadChunk(0, 0);

    for (int kc = 0; kc < NKC; kc++) {
        const int buf = kc & 1;
        if (kc + 1 < NKC) { loadChunk(kc + 1, buf ^ 1); cp_wait<1>(); }
        else              { cp_wait<0>(); }
        __syncthreads();

        const uint32_t aB[2] = { sb + OFF_A + (buf * 2 + 0) * 16384,
                                 sb + OFF_A + (buf * 2 + 1) * 16384 };
        const uint32_t bB[2] = { sb + OFF_B + (buf * 2 + 0) * 16384,
                                 sb + OFF_B + (buf * 2 + 1) * 16384 };
        const int aH[3] = {0, 0, 1};
        const int bH[3] = {0, 1, 0};

#pragma unroll
        for (int p = 0; p < 3; p++) {
            const uint32_t ab = aB[aH[p]];
            const uint32_t bb = bB[bH[p]];
#pragma unroll
            for (int ks = 0; ks < 4; ks++) {
                uint32_t a[4][4], b[2][4];
#pragma unroll
                for (int i = 0; i < 4; i++)
                    ldsm_x4(a[i], ab + SW128(aOff[i] + ks * 32));
#pragma unroll
                for (int jj = 0; jj < 2; jj++)
                    ldsm_x4(b[jj], bb + SW128(bOff[jj] + ks * 32));
#pragma unroll
                for (int i = 0; i < 4; i++)
#pragma unroll
                    for (int j = 0; j < 4; j++)
                        mma16816(acc[i][j], a[i], b[j >> 1][j & 1], b[j >> 1][(j & 1) + 2]);
            }
        }
        __syncthreads();   // all warps done with buf before it is refilled
    }

    // Epilogue: c0 (r,c) c1 (r,c+1) c2 (r+8,c) c3 (r+8,c+1); r = lane/4, c = 2*(lane%4)
    const int tig = lane & 3;
    const int grp = lane >> 2;
    const float* brow = eb + e * D + n0 + wn;
#pragma unroll
    for (int i = 0; i < 4; i++) {
#pragma unroll
        for (int h = 0; h < 2; h++) {
            int r = wm + 16 * i + grp + h * 8;
            int gr = m0 + r;
            if (gr < rows) {
                int tok = sTok[r];
                float w = sW[r];
                float* orow = out + (size_t)tok * D + n0 + wn;
#pragma unroll
                for (int j = 0; j < 4; j++) {
                    int col = 8 * j + 2 * tig;
                    atomicAdd(&orow[col],     w * (acc[i][j][h * 2 + 0] + brow[col]));
                    atomicAdd(&orow[col + 1], w * (acc[i][j][h * 2 + 1] + brow[col + 1]));
                }
            }
        }
    }
}

// ---------------------------------------------------------------------------
extern "C" void kernel_launch(void* const* d_in, const int* in_sizes, int n_in,
                              void* d_out, int out_size) {
    const float* x  = (const float*)d_in[0];
    const float* gw = (const float*)d_in[1];
    const float* gb = (const float*)d_in[2];
    const float* ew = (const float*)d_in[3];
    const float* eb = (const float*)d_in[4];
    float* out = (float*)d_out;

    const int T = in_sizes[0] / D;

    cudaFuncSetAttribute(moe_mma, cudaFuncAttributeMaxDynamicSharedMemorySize,
                         SMEM_BYTES);

    cudaMemsetAsync(out, 0, (size_t)out_size * sizeof(float), 0);
    init_kernel<<<1, 32>>>();

    {   // gating
        int threads = 256;
        int blocks = (T * 32 + threads - 1) / threads;
        gate_kernel<<<blocks, threads>>>(x, gw, gb, T);
    }
    {   // input split
        int n4 = T * D / 4;
        convert_x<<<(n4 + 255) / 256, 256>>>(x, n4);
    }
    {   // weight transpose + split
        dim3 grid(D / 32, D / 32, E_TRUE);
        convert_w<<<grid, dim3(32, 32)>>>(ew);
    }
    {   // grouped HMMA GEMM
        dim3 grid(D / BN, (T + BM - 1) / BM, E_TRUE);
        moe_mma<<<grid, 256, SMEM_BYTES>>>(eb, out);
    }
}

// round 10
// speedup vs baseline: 2.7027x; 1.3864x over previous
#include <cuda_runtime.h>
#include <cuda_fp16.h>
#include <math.h>
#include <stdint.h>

#define D        1024
#define E_TOT    10
#define E_TRUE   8
#define MAX_T    8192
#define BM       128
#define BN       128
#define KT       64        // k-chunk: 64 fp16 = 128 bytes = one SW128 row
#define NKC      (D / KT)  // 16 chunks
#define W_SCALE      1024.0f
#define W_INV_SCALE  (1.0f / 1024.0f)

// ---------------- device scratch (__device__ globals) ----------------------
__device__ int   g_cnt[E_TRUE];
__device__ int   g_tok[E_TRUE * MAX_T];
__device__ float g_wt [E_TRUE * MAX_T];
__device__ __half g_xhi[MAX_T * D];
__device__ __half g_xlo[MAX_T * D];
__device__ __half g_w  [E_TRUE * D * D];   // [e][n][k] transposed, x1024

// ---------------- PTX helpers (<= sm_90 baseline features only) ------------
__device__ __forceinline__ uint32_t smem_u32(const void* p) {
    uint32_t a;
    asm("{ .reg .u64 t; cvta.to.shared.u64 t, %1; cvt.u32.u64 %0, t; }"
        : "=r"(a) : "l"(p));
    return a;
}
#define SW128(off) ((off) ^ (((off) >> 3) & 0x70))

__device__ __forceinline__ void cp16(uint32_t dst, const void* src) {
    asm volatile("cp.async.cg.shared.global [%0], [%1], 16;"
                 :: "r"(dst), "l"(__cvta_generic_to_global(src)));
}
__device__ __forceinline__ void cp_commit() {
    asm volatile("cp.async.commit_group;");
}
template <int N>
__device__ __forceinline__ void cp_wait() {
    asm volatile("cp.async.wait_group %0;" :: "n"(N));
}
__device__ __forceinline__ void ldsm_x4(uint32_t* r, uint32_t addr) {
    asm volatile("ldmatrix.sync.aligned.m8n8.x4.shared.b16 {%0,%1,%2,%3}, [%4];"
                 : "=r"(r[0]), "=r"(r[1]), "=r"(r[2]), "=r"(r[3]) : "r"(addr));
}
__device__ __forceinline__ void mma16816(float* d, const uint32_t* a,
                                         uint32_t b0, uint32_t b1) {
    asm volatile(
        "mma.sync.aligned.m16n8k16.row.col.f32.f16.f16.f32 "
        "{%0,%1,%2,%3}, {%4,%5,%6,%7}, {%8,%9}, {%0,%1,%2,%3};"
        : "+f"(d[0]), "+f"(d[1]), "+f"(d[2]), "+f"(d[3])
        : "r"(a[0]), "r"(a[1]), "r"(a[2]), "r"(a[3]), "r"(b0), "r"(b1));
}

// ---------------- SMEM layout ----------------------------------------------
#define OFF_TOK  0                   // 128 ints
#define OFF_W    512                 // 128 floats
#define OFF_A    1024                // A(buf,half): 4 x 16KB
#define OFF_B    (1024 + 4*16384)    // B(buf): 2 x 16KB
#define SMEM_BYTES (OFF_B + 2*16384) // 99328

// ---------------------------------------------------------------------------
__global__ void init_kernel() {
    if (threadIdx.x < E_TRUE) g_cnt[threadIdx.x] = 0;
}

// One warp per token: gating, softmax, top-2, null-mask, renorm, scatter.
__global__ void gate_kernel(const float* __restrict__ x,
                            const float* __restrict__ gw,
                            const float* __restrict__ gb, int T) {
    int gtid = blockIdx.x * blockDim.x + threadIdx.x;
    int t = gtid >> 5;
    int lane = gtid & 31;
    if (t >= T) return;
    const float* xr = x + (size_t)t * D;

    float dot[E_TOT];
#pragma unroll
    for (int e = 0; e < E_TOT; e++) dot[e] = 0.f;
    for (int i = lane; i < D; i += 32) {
        float xv = xr[i];
#pragma unroll
        for (int e = 0; e < E_TOT; e++) dot[e] += xv * gw[e * D + i];
    }
#pragma unroll
    for (int e = 0; e < E_TOT; e++) {
#pragma unroll
        for (int off = 16; off; off >>= 1)
            dot[e] += __shfl_xor_sync(0xffffffffu, dot[e], off);
    }
    if (lane == 0) {
        float p[E_TOT];
        float mx = -1e30f;
#pragma unroll
        for (int e = 0; e < E_TOT; e++) { p[e] = dot[e] + gb[e]; mx = fmaxf(mx, p[e]); }
        float s = 0.f;
#pragma unroll
        for (int e = 0; e < E_TOT; e++) { p[e] = expf(p[e] - mx); s += p[e]; }
        int i1 = 0;
#pragma unroll
        for (int e = 1; e < E_TOT; e++) if (p[e] > p[i1]) i1 = e;
        int i2 = (i1 == 0) ? 1 : 0;
#pragma unroll
        for (int e = 0; e < E_TOT; e++) if (e != i1 && p[e] > p[i2]) i2 = e;

        float w1 = p[i1] / s, w2 = p[i2] / s;
        float t1 = (i1 < E_TRUE) ? w1 : 0.f;
        float t2 = (i2 < E_TRUE) ? w2 : 0.f;
        float den = t1 + t2;
        den = (den > 0.f) ? den : 1.f;
        t1 /= den; t2 /= den;
        if (i1 < E_TRUE) {
            int pos = atomicAdd(&g_cnt[i1], 1);
            g_tok[i1 * MAX_T + pos] = t;  g_wt[i1 * MAX_T + pos] = t1;
        }
        if (i2 < E_TRUE) {
            int pos = atomicAdd(&g_cnt[i2], 1);
            g_tok[i2 * MAX_T + pos] = t;  g_wt[i2 * MAX_T + pos] = t2;
        }
    }
}

// x fp32 -> (hi, lo) fp16
__global__ void convert_x(const float* __restrict__ x, int n4) {
    int i = blockIdx.x * blockDim.x + threadIdx.x;
    if (i >= n4) return;
    float4 v = ((const float4*)x)[i];
    __half h0 = __float2half_rn(v.x);
    __half h1 = __float2half_rn(v.y);
    __half h2 = __float2half_rn(v.z);
    __half h3 = __float2half_rn(v.w);
    __half l0 = __float2half_rn(v.x - __half2float(h0));
    __half l1 = __float2half_rn(v.y - __half2float(h1));
    __half l2 = __float2half_rn(v.z - __half2float(h2));
    __half l3 = __float2half_rn(v.w - __half2float(h3));
    __half2* ph = (__half2*)g_xhi;
    __half2* pl = (__half2*)g_xlo;
    ph[2*i]   = __halves2half2(h0, h1);
    ph[2*i+1] = __halves2half2(h2, h3);
    pl[2*i]   = __halves2half2(l0, l1);
    pl[2*i+1] = __halves2half2(l2, l3);
}

// ew[e][k][n] fp32 -> transposed fp16 [e][n][k] x 1024.
// 64x64 tiles, 256 threads, float4 loads, uint2 (4 x fp16) stores.
__global__ __launch_bounds__(256)
void convert_w(const float* __restrict__ ew) {
    __shared__ float tile[64][65];
    const int e  = blockIdx.z;
    const int n0 = blockIdx.x * 64;
    const int k0 = blockIdx.y * 64;
    const int tid = threadIdx.x;
    const int seg = tid & 15;      // float4 column / k-quad
    const int row = tid >> 4;      // 16 rows per pass

    const float* src = ew + (size_t)e * D * D;
#pragma unroll
    for (int p = 0; p < 4; p++) {
        int k = row + p * 16;
        float4 v = *(const float4*)(src + (size_t)(k0 + k) * D + n0 + seg * 4);
        tile[k][seg * 4 + 0] = v.x;
        tile[k][seg * 4 + 1] = v.y;
        tile[k][seg * 4 + 2] = v.z;
        tile[k][seg * 4 + 3] = v.w;
    }
    __syncthreads();

    __half* dst = g_w + (size_t)e * D * D;
#pragma unroll
    for (int p = 0; p < 4; p++) {
        int n = row + p * 16;
        int kk = seg * 4;
        __half2 h01 = __floats2half2_rn(tile[kk + 0][n] * W_SCALE,
                                        tile[kk + 1][n] * W_SCALE);
        __half2 h23 = __floats2half2_rn(tile[kk + 2][n] * W_SCALE,
                                        tile[kk + 3][n] * W_SCALE);
        uint2 pk;
        pk.x = *(uint32_t*)&h01;
        pk.y = *(uint32_t*)&h23;
        *(uint2*)(dst + (size_t)(n0 + n) * D + k0 + kk) = pk;
    }
}

// ---------------------------------------------------------------------------
// Grouped fp16 split-x HMMA GEMM. grid = (N/BN, maxMtiles, E_TRUE), 256 thr.
// out = (A_hi + A_lo) * B, fp32 accum. Warp tile 64x32, mma.m16n8k16.
__global__ __launch_bounds__(256, 1)
void moe_mma(const float* __restrict__ eb, float* __restrict__ out) {
    extern __shared__ __align__(1024) char smem[];
    const int e = blockIdx.z;
    const int rows = g_cnt[e];
    const int m0 = blockIdx.y * BM;
    if (m0 >= rows) return;
    const int n0 = blockIdx.x * BN;

    const uint32_t sb = smem_u32(smem);
    const int tid = threadIdx.x;
    const int wid = tid >> 5;
    const int lane = tid & 31;
    const int wm = (wid >> 2) * 64;
    const int wn = (wid & 3) * 32;

    int*   sTok = (int*)(smem + OFF_TOK);
    float* sW   = (float*)(smem + OFF_W);
    if (tid < BM) {
        int gr = m0 + tid;
        sTok[tid] = (gr < rows) ? g_tok[e * MAX_T + gr] : 0;
        sW[tid]   = (gr < rows) ? g_wt [e * MAX_T + gr] : 0.f;
    }
    __syncthreads();

    const __half* xsrc[2] = { g_xhi, g_xlo };
    const __half* wsrc = g_w + (size_t)e * D * D;

    int cRow[4], cGrp[4];
    uint32_t cSw[4];
#pragma unroll
    for (int t = 0; t < 4; t++) {
        int c = tid + t * 256;
        cRow[t] = c >> 3;
        cGrp[t] = c & 7;
        cSw[t]  = SW128((uint32_t)(cRow[t] * 128 + cGrp[t] * 16));
    }

    auto loadChunk = [&](int kc, int buf) {
        const int k0 = kc * KT;
        uint32_t bbase = sb + OFF_B + buf * 16384;
#pragma unroll
        for (int half = 0; half < 2; half++) {
            uint32_t abase = sb + OFF_A + (buf * 2 + half) * 16384;
#pragma unroll
            for (int t = 0; t < 4; t++)
                cp16(abase + cSw[t],
                     xsrc[half] + (size_t)sTok[cRow[t]] * D + k0 + cGrp[t] * 8);
        }
#pragma unroll
        for (int t = 0; t < 4; t++)
            cp16(bbase + cSw[t],
                 wsrc + (size_t)(n0 + cRow[t]) * D + k0 + cGrp[t] * 8);
        cp_commit();
    };

    // ldmatrix per-lane pre-swizzle offsets (k-invariant part)
    uint32_t aOff[4], bOff[2];
#pragma unroll
    for (int i = 0; i < 4; i++)
        aOff[i] = (uint32_t)((wm + 16 * i + (lane & 15)) * 128 + (lane >> 4) * 16);
#pragma unroll
    for (int jj = 0; jj < 2; jj++)
        bOff[jj] = (uint32_t)((wn + 16 * jj + ((lane >> 3) & 1) * 8 + (lane & 7)) * 128
                              + (lane >> 4) * 16);

    float acc[4][4][4];
#pragma unroll
    for (int i = 0; i < 4; i++)
#pragma unroll
        for (int j = 0; j < 4; j++)
#pragma unroll
            for (int r = 0; r < 4; r++) acc[i][j][r] = 0.f;

    loadChunk(0, 0);

    for (int kc = 0; kc < NKC; kc++) {
        const int buf = kc & 1;
        if (kc + 1 < NKC) { loadChunk(kc + 1, buf ^ 1); cp_wait<1>(); }
        else              { cp_wait<0>(); }
        __syncthreads();

        const uint32_t aB[2] = { sb + OFF_A + (buf * 2 + 0) * 16384,
                                 sb + OFF_A + (buf * 2 + 1) * 16384 };
        const uint32_t bb   =   sb + OFF_B + buf * 16384;

#pragma unroll
        for (int ks = 0; ks < 4; ks++) {
            uint32_t b[2][4];
#pragma unroll
            for (int jj = 0; jj < 2; jj++)
                ldsm_x4(b[jj], bb + SW128(bOff[jj] + ks * 32));
            // both x halves accumulate into the same fp32 accumulator
#pragma unroll
            for (int half = 0; half < 2; half++) {
                uint32_t a[4][4];
#pragma unroll
                for (int i = 0; i < 4; i++)
                    ldsm_x4(a[i], aB[half] + SW128(aOff[i] + ks * 32));
#pragma unroll
                for (int i = 0; i < 4; i++)
#pragma unroll
                    for (int j = 0; j < 4; j++)
                        mma16816(acc[i][j], a[i],
                                 b[j >> 1][j & 1], b[j >> 1][(j & 1) + 2]);
            }
        }
        __syncthreads();
    }

    // Epilogue: undo W_SCALE, add bias, apply gate weight, scatter-atomic.
    const int tig = lane & 3;
    const int grp = lane >> 2;
    const float* brow = eb + e * D + n0 + wn;
#pragma unroll
    for (int i = 0; i < 4; i++) {
#pragma unroll
        for (int h = 0; h < 2; h++) {
            int r = wm + 16 * i + grp + h * 8;
            int gr = m0 + r;
            if (gr < rows) {
                int tok = sTok[r];
                float w = sW[r];
                float* orow = out + (size_t)tok * D + n0 + wn;
#pragma unroll
                for (int j = 0; j < 4; j++) {
                    int col = 8 * j + 2 * tig;
                    float y0 = acc[i][j][h * 2 + 0] * W_INV_SCALE;
                    float y1 = acc[i][j][h * 2 + 1] * W_INV_SCALE;
                    atomicAdd(&orow[col],     w * (y0 + brow[col]));
                    atomicAdd(&orow[col + 1], w * (y1 + brow[col + 1]));
                }
            }
        }
    }
}

// ---------------------------------------------------------------------------
extern "C" void kernel_launch(void* const* d_in, const int* in_sizes, int n_in,
                              void* d_out, int out_size) {
    const float* x  = (const float*)d_in[0];
    const float* gw = (const float*)d_in[1];
    const float* gb = (const float*)d_in[2];
    const float* ew = (const float*)d_in[3];
    const float* eb = (const float*)d_in[4];
    float* out = (float*)d_out;

    const int T = in_sizes[0] / D;

    cudaFuncSetAttribute(moe_mma, cudaFuncAttributeMaxDynamicSharedMemorySize,
                         SMEM_BYTES);

    cudaMemsetAsync(out, 0, (size_t)out_size * sizeof(float), 0);
    init_kernel<<<1, 32>>>();

    {   // weight transpose + fp16 convert (longest independent prologue first)
        dim3 grid(D / 64, D / 64, E_TRUE);
        convert_w<<<grid, 256>>>(ew);
    }
    {   // gating
        int threads = 256;
        int blocks = (T * 32 + threads - 1) / threads;
        gate_kernel<<<blocks, threads>>>(x, gw, gb, T);
    }
    {   // input split
        int n4 = T * D / 4;
        convert_x<<<(n4 + 255) / 256, 256>>>(x, n4);
    }
    {   // grouped HMMA GEMM
        dim3 grid(D / BN, (T + BM - 1) / BM, E_TRUE);
        moe_mma<<<grid, 256, SMEM_BYTES>>>(eb, out);
    }
}

// round 11
// speedup vs baseline: 4.3651x; 1.6151x over previous
#include <cuda_runtime.h>
#include <cuda_fp16.h>
#include <math.h>
#include <stdint.h>

#define D        1024
#define E_TOT    10
#define E_TRUE   8
#define MAX_T    8192
#define BM       128
#define BN       128
#define KT       64        // k-chunk: 64 fp16 = 128 bytes = one SW128 row
#define NKC      (D / KT)  // 16 chunks
#define W_SCALE      1024.0f
#define W_INV_SCALE  (1.0f / 1024.0f)

// ---------------- device scratch (__device__ globals) ----------------------
__device__ int   g_cnt[E_TRUE];
__device__ int   g_tok[E_TRUE * MAX_T];
__device__ float g_wt [E_TRUE * MAX_T];
__device__ __half g_x  [MAX_T * D];        // fp16(x)
__device__ __half g_w  [E_TRUE * D * D];   // [e][n][k] transposed, x1024

// ---------------- PTX helpers (<= sm_90 baseline features only) ------------
__device__ __forceinline__ uint32_t smem_u32(const void* p) {
    uint32_t a;
    asm("{ .reg .u64 t; cvta.to.shared.u64 t, %1; cvt.u32.u64 %0, t; }"
        : "=r"(a) : "l"(p));
    return a;
}
#define SW128(off) ((off) ^ (((off) >> 3) & 0x70))

__device__ __forceinline__ void cp16(uint32_t dst, const void* src) {
    asm volatile("cp.async.cg.shared.global [%0], [%1], 16;"
                 :: "r"(dst), "l"(__cvta_generic_to_global(src)));
}
__device__ __forceinline__ void cp_commit() {
    asm volatile("cp.async.commit_group;");
}
template <int N>
__device__ __forceinline__ void cp_wait() {
    asm volatile("cp.async.wait_group %0;" :: "n"(N));
}
__device__ __forceinline__ void ldsm_x4(uint32_t* r, uint32_t addr) {
    asm volatile("ldmatrix.sync.aligned.m8n8.x4.shared.b16 {%0,%1,%2,%3}, [%4];"
                 : "=r"(r[0]), "=r"(r[1]), "=r"(r[2]), "=r"(r[3]) : "r"(addr));
}
__device__ __forceinline__ void mma16816(float* d, const uint32_t* a,
                                         uint32_t b0, uint32_t b1) {
    asm volatile(
        "mma.sync.aligned.m16n8k16.row.col.f32.f16.f16.f32 "
        "{%0,%1,%2,%3}, {%4,%5,%6,%7}, {%8,%9}, {%0,%1,%2,%3};"
        : "+f"(d[0]), "+f"(d[1]), "+f"(d[2]), "+f"(d[3])
        : "r"(a[0]), "r"(a[1]), "r"(a[2]), "r"(a[3]), "r"(b0), "r"(b1));
}

// ---------------- SMEM layout ----------------------------------------------
#define OFF_TOK  0                   // 128 ints
#define OFF_W    512                 // 128 floats
#define OFF_A    1024                // A(buf): 2 x 16KB
#define OFF_B    (1024 + 2*16384)    // B(buf): 2 x 16KB
#define SMEM_BYTES (OFF_B + 2*16384) // 66560 -> 2 CTAs/SM

// ---------------------------------------------------------------------------
__global__ void init_kernel() {
    if (threadIdx.x < E_TRUE) g_cnt[threadIdx.x] = 0;
}

// One warp per token: gating, softmax, top-2, null-mask, renorm, scatter.
__global__ void gate_kernel(const float* __restrict__ x,
                            const float* __restrict__ gw,
                            const float* __restrict__ gb, int T) {
    int gtid = blockIdx.x * blockDim.x + threadIdx.x;
    int t = gtid >> 5;
    int lane = gtid & 31;
    if (t >= T) return;
    const float* xr = x + (size_t)t * D;

    float dot[E_TOT];
#pragma unroll
    for (int e = 0; e < E_TOT; e++) dot[e] = 0.f;
    for (int i = lane; i < D; i += 32) {
        float xv = xr[i];
#pragma unroll
        for (int e = 0; e < E_TOT; e++) dot[e] += xv * gw[e * D + i];
    }
#pragma unroll
    for (int e = 0; e < E_TOT; e++) {
#pragma unroll
        for (int off = 16; off; off >>= 1)
            dot[e] += __shfl_xor_sync(0xffffffffu, dot[e], off);
    }
    if (lane == 0) {
        float p[E_TOT];
        float mx = -1e30f;
#pragma unroll
        for (int e = 0; e < E_TOT; e++) { p[e] = dot[e] + gb[e]; mx = fmaxf(mx, p[e]); }
        float s = 0.f;
#pragma unroll
        for (int e = 0; e < E_TOT; e++) { p[e] = expf(p[e] - mx); s += p[e]; }
        int i1 = 0;
#pragma unroll
        for (int e = 1; e < E_TOT; e++) if (p[e] > p[i1]) i1 = e;
        int i2 = (i1 == 0) ? 1 : 0;
#pragma unroll
        for (int e = 0; e < E_TOT; e++) if (e != i1 && p[e] > p[i2]) i2 = e;

        float w1 = p[i1] / s, w2 = p[i2] / s;
        float t1 = (i1 < E_TRUE) ? w1 : 0.f;
        float t2 = (i2 < E_TRUE) ? w2 : 0.f;
        float den = t1 + t2;
        den = (den > 0.f) ? den : 1.f;
        t1 /= den; t2 /= den;
        if (i1 < E_TRUE) {
            int pos = atomicAdd(&g_cnt[i1], 1);
            g_tok[i1 * MAX_T + pos] = t;  g_wt[i1 * MAX_T + pos] = t1;
        }
        if (i2 < E_TRUE) {
            int pos = atomicAdd(&g_cnt[i2], 1);
            g_tok[i2 * MAX_T + pos] = t;  g_wt[i2 * MAX_T + pos] = t2;
        }
    }
}

// x fp32 -> fp16
__global__ void convert_x(const float* __restrict__ x, int n4) {
    int i = blockIdx.x * blockDim.x + threadIdx.x;
    if (i >= n4) return;
    float4 v = ((const float4*)x)[i];
    __half2 h01 = __floats2half2_rn(v.x, v.y);
    __half2 h23 = __floats2half2_rn(v.z, v.w);
    uint2 pk;
    pk.x = *(uint32_t*)&h01;
    pk.y = *(uint32_t*)&h23;
    *(uint2*)(g_x + (size_t)i * 4) = pk;
}

// ew[e][k][n] fp32 -> transposed fp16 [e][n][k] x 1024.
// 64x64 tiles, 256 threads, float4 loads, uint2 (4 x fp16) stores.
__global__ __launch_bounds__(256)
void convert_w(const float* __restrict__ ew) {
    __shared__ float tile[64][65];
    const int e  = blockIdx.z;
    const int n0 = blockIdx.x * 64;
    const int k0 = blockIdx.y * 64;
    const int tid = threadIdx.x;
    const int seg = tid & 15;
    const int row = tid >> 4;

    const float* src = ew + (size_t)e * D * D;
#pragma unroll
    for (int p = 0; p < 4; p++) {
        int k = row + p * 16;
        float4 v = *(const float4*)(src + (size_t)(k0 + k) * D + n0 + seg * 4);
        tile[k][seg * 4 + 0] = v.x;
        tile[k][seg * 4 + 1] = v.y;
        tile[k][seg * 4 + 2] = v.z;
        tile[k][seg * 4 + 3] = v.w;
    }
    __syncthreads();

    __half* dst = g_w + (size_t)e * D * D;
#pragma unroll
    for (int p = 0; p < 4; p++) {
        int n = row + p * 16;
        int kk = seg * 4;
        __half2 h01 = __floats2half2_rn(tile[kk + 0][n] * W_SCALE,
                                        tile[kk + 1][n] * W_SCALE);
        __half2 h23 = __floats2half2_rn(tile[kk + 2][n] * W_SCALE,
                                        tile[kk + 3][n] * W_SCALE);
        uint2 pk;
        pk.x = *(uint32_t*)&h01;
        pk.y = *(uint32_t*)&h23;
        *(uint2*)(dst + (size_t)(n0 + n) * D + k0 + kk) = pk;
    }
}

// ---------------------------------------------------------------------------
// Grouped fp16 HMMA GEMM (single pass). grid = (N/BN, maxMtiles, E_TRUE).
// Warp tile 64x32, mma.m16n8k16, fp32 accum, occ 2.
__global__ __launch_bounds__(256, 2)
void moe_mma(const float* __restrict__ eb, float* __restrict__ out) {
    extern __shared__ __align__(1024) char smem[];
    const int e = blockIdx.z;
    const int rows = g_cnt[e];
    const int m0 = blockIdx.y * BM;
    if (m0 >= rows) return;
    const int n0 = blockIdx.x * BN;

    const uint32_t sb = smem_u32(smem);
    const int tid = threadIdx.x;
    const int wid = tid >> 5;
    const int lane = tid & 31;
    const int wm = (wid >> 2) * 64;
    const int wn = (wid & 3) * 32;

    int*   sTok = (int*)(smem + OFF_TOK);
    float* sW   = (float*)(smem + OFF_W);
    if (tid < BM) {
        int gr = m0 + tid;
        sTok[tid] = (gr < rows) ? g_tok[e * MAX_T + gr] : 0;
        sW[tid]   = (gr < rows) ? g_wt [e * MAX_T + gr] : 0.f;
    }
    __syncthreads();

    const __half* wsrc = g_w + (size_t)e * D * D;

    int cRow[4], cGrp[4];
    uint32_t cSw[4];
#pragma unroll
    for (int t = 0; t < 4; t++) {
        int c = tid + t * 256;
        cRow[t] = c >> 3;
        cGrp[t] = c & 7;
        cSw[t]  = SW128((uint32_t)(cRow[t] * 128 + cGrp[t] * 16));
    }

    auto loadChunk = [&](int kc, int buf) {
        const int k0 = kc * KT;
        uint32_t abase = sb + OFF_A + buf * 16384;
        uint32_t bbase = sb + OFF_B + buf * 16384;
#pragma unroll
        for (int t = 0; t < 4; t++) {
            cp16(abase + cSw[t],
                 g_x + (size_t)sTok[cRow[t]] * D + k0 + cGrp[t] * 8);
            cp16(bbase + cSw[t],
                 wsrc + (size_t)(n0 + cRow[t]) * D + k0 + cGrp[t] * 8);
        }
        cp_commit();
    };

    // ldmatrix per-lane pre-swizzle offsets (k-invariant part)
    uint32_t aOff[4], bOff[2];
#pragma unroll
    for (int i = 0; i < 4; i++)
        aOff[i] = (uint32_t)((wm + 16 * i + (lane & 15)) * 128 + (lane >> 4) * 16);
#pragma unroll
    for (int jj = 0; jj < 2; jj++)
        bOff[jj] = (uint32_t)((wn + 16 * jj + ((lane >> 3) & 1) * 8 + (lane & 7)) * 128
                              + (lane >> 4) * 16);

    float acc[4][4][4];
#pragma unroll
    for (int i = 0; i < 4; i++)
#pragma unroll
        for (int j = 0; j < 4; j++)
#pragma unroll
            for (int r = 0; r < 4; r++) acc[i][j][r] = 0.f;

    loadChunk(0, 0);

    for (int kc = 0; kc < NKC; kc++) {
        const int buf = kc & 1;
        if (kc + 1 < NKC) { loadChunk(kc + 1, buf ^ 1); cp_wait<1>(); }
        else              { cp_wait<0>(); }
        __syncthreads();

        const uint32_t ab = sb + OFF_A + buf * 16384;
        const uint32_t bb = sb + OFF_B + buf * 16384;

#pragma unroll
        for (int ks = 0; ks < 4; ks++) {
            uint32_t b[2][4];
#pragma unroll
            for (int jj = 0; jj < 2; jj++)
                ldsm_x4(b[jj], bb + SW128(bOff[jj] + ks * 32));
            uint32_t a[4][4];
#pragma unroll
            for (int i = 0; i < 4; i++)
                ldsm_x4(a[i], ab + SW128(aOff[i] + ks * 32));
#pragma unroll
            for (int i = 0; i < 4; i++)
#pragma unroll
                for (int j = 0; j < 4; j++)
                    mma16816(acc[i][j], a[i],
                             b[j >> 1][j & 1], b[j >> 1][(j & 1) + 2]);
        }
        __syncthreads();
    }

    // Epilogue: undo W_SCALE, add bias, apply gate weight, scatter-atomic.
    const int tig = lane & 3;
    const int grp = lane >> 2;
    const float* brow = eb + e * D + n0 + wn;
#pragma unroll
    for (int i = 0; i < 4; i++) {
#pragma unroll
        for (int h = 0; h < 2; h++) {
            int r = wm + 16 * i + grp + h * 8;
            int gr = m0 + r;
            if (gr < rows) {
                int tok = sTok[r];
                float w = sW[r];
                float* orow = out + (size_t)tok * D + n0 + wn;
#pragma unroll
                for (int j = 0; j < 4; j++) {
                    int col = 8 * j + 2 * tig;
                    float y0 = acc[i][j][h * 2 + 0] * W_INV_SCALE;
                    float y1 = acc[i][j][h * 2 + 1] * W_INV_SCALE;
                    atomicAdd(&orow[col],     w * (y0 + brow[col]));
                    atomicAdd(&orow[col + 1], w * (y1 + brow[col + 1]));
                }
            }
        }
    }
}

// ---------------------------------------------------------------------------
extern "C" void kernel_launch(void* const* d_in, const int* in_sizes, int n_in,
                              void* d_out, int out_size) {
    const float* x  = (const float*)d_in[0];
    const float* gw = (const float*)d_in[1];
    const float* gb = (const float*)d_in[2];
    const float* ew = (const float*)d_in[3];
    const float* eb = (const float*)d_in[4];
    float* out = (float*)d_out;

    const int T = in_sizes[0] / D;

    cudaFuncSetAttribute(moe_mma, cudaFuncAttributeMaxDynamicSharedMemorySize,
                         SMEM_BYTES);

    cudaMemsetAsync(out, 0, (size_t)out_size * sizeof(float), 0);
    init_kernel<<<1, 32>>>();

    {   // weight transpose + fp16 convert
        dim3 grid(D / 64, D / 64, E_TRUE);
        convert_w<<<grid, 256>>>(ew);
    }
    {   // gating
        int threads = 256;
        int blocks = (T * 32 + threads - 1) / threads;
        gate_kernel<<<blocks, threads>>>(x, gw, gb, T);
    }
    {   // input fp16 convert
        int n4 = T * D / 4;
        convert_x<<<(n4 + 255) / 256, 256>>>(x, n4);
    }
    {   // grouped HMMA GEMM (single pass)
        dim3 grid(D / BN, (T + BM - 1) / BM, E_TRUE);
        moe_mma<<<grid, 256, SMEM_BYTES>>>(eb, out);
    }
}

// round 12
// speedup vs baseline: 4.7246x; 1.0824x over previous
#include <cuda_runtime.h>
#include <cuda_fp16.h>
#include <math.h>
#include <stdint.h>

#define D        1024
#define E_TOT    10
#define E_TRUE   8
#define MAX_T    8192
#define BM       128
#define BN       128
#define KT       64        // k-chunk: 64 fp16 = 128 bytes = one SW128 row
#define NKC      (D / KT)  // 16 chunks
#define W_SCALE      1024.0f
#define W_INV_SCALE  (1.0f / 1024.0f)

// ---------------- device scratch (__device__ globals) ----------------------
__device__ int   g_cnt[E_TRUE];
__device__ int   g_tok[E_TRUE * MAX_T];
__device__ float g_wt [E_TRUE * MAX_T];
__device__ __half g_x  [MAX_T * D];        // fp16(x)
__device__ __half g_w  [E_TRUE * D * D];   // [e][n][k] transposed, x1024

// ---------------- PTX helpers (<= sm_90 baseline features only) ------------
__device__ __forceinline__ uint32_t smem_u32(const void* p) {
    uint32_t a;
    asm("{ .reg .u64 t; cvta.to.shared.u64 t, %1; cvt.u32.u64 %0, t; }"
        : "=r"(a) : "l"(p));
    return a;
}
#define SW128(off) ((off) ^ (((off) >> 3) & 0x70))

__device__ __forceinline__ void cp16(uint32_t dst, const void* src) {
    asm volatile("cp.async.cg.shared.global [%0], [%1], 16;"
                 :: "r"(dst), "l"(__cvta_generic_to_global(src)));
}
__device__ __forceinline__ void cp_commit() {
    asm volatile("cp.async.commit_group;");
}
template <int N>
__device__ __forceinline__ void cp_wait() {
    asm volatile("cp.async.wait_group %0;" :: "n"(N));
}
__device__ __forceinline__ void ldsm_x4(uint32_t* r, uint32_t addr) {
    asm volatile("ldmatrix.sync.aligned.m8n8.x4.shared.b16 {%0,%1,%2,%3}, [%4];"
                 : "=r"(r[0]), "=r"(r[1]), "=r"(r[2]), "=r"(r[3]) : "r"(addr));
}
__device__ __forceinline__ void mma16816(float* d, const uint32_t* a,
                                         uint32_t b0, uint32_t b1) {
    asm volatile(
        "mma.sync.aligned.m16n8k16.row.col.f32.f16.f16.f32 "
        "{%0,%1,%2,%3}, {%4,%5,%6,%7}, {%8,%9}, {%0,%1,%2,%3};"
        : "+f"(d[0]), "+f"(d[1]), "+f"(d[2]), "+f"(d[3])
        : "r"(a[0]), "r"(a[1]), "r"(a[2]), "r"(a[3]), "r"(b0), "r"(b1));
}

// ---------------- SMEM layout ----------------------------------------------
#define OFF_TOK  0                   // 128 ints
#define OFF_W    512                 // 128 floats
#define OFF_A    1024                // A(buf): 2 x 16KB
#define OFF_B    (1024 + 2*16384)    // B(buf): 2 x 16KB
#define SMEM_BYTES (OFF_B + 2*16384) // 66560 -> 2 CTAs/SM

// ---------------------------------------------------------------------------
// Fused gating + fp16 conversion of x. One warp per token:
// float4-vectorized row read, fp16 row write, 10 dots, softmax, top-2,
// null-mask, renorm, scatter into per-expert lists.
__global__ void gate_kernel(const float* __restrict__ x,
                            const float* __restrict__ gw,
                            const float* __restrict__ gb, int T) {
    int gtid = blockIdx.x * blockDim.x + threadIdx.x;
    int t = gtid >> 5;
    int lane = gtid & 31;
    if (t >= T) return;
    const float4* xr  = (const float4*)(x + (size_t)t * D);
    const float4* gw4 = (const float4*)gw;

    float dot[E_TOT];
#pragma unroll
    for (int e = 0; e < E_TOT; e++) dot[e] = 0.f;

#pragma unroll
    for (int p = 0; p < 8; p++) {
        int f = p * 32 + lane;              // float4 index within row
        float4 v = xr[f];
        __half2 h01 = __floats2half2_rn(v.x, v.y);
        __half2 h23 = __floats2half2_rn(v.z, v.w);
        uint2 pk;
        pk.x = *(uint32_t*)&h01;
        pk.y = *(uint32_t*)&h23;
        *(uint2*)(g_x + (size_t)t * D + f * 4) = pk;
#pragma unroll
        for (int e = 0; e < E_TOT; e++) {
            float4 w = gw4[e * (D / 4) + f];
            dot[e] += v.x * w.x + v.y * w.y + v.z * w.z + v.w * w.w;
        }
    }
#pragma unroll
    for (int e = 0; e < E_TOT; e++) {
#pragma unroll
        for (int off = 16; off; off >>= 1)
            dot[e] += __shfl_xor_sync(0xffffffffu, dot[e], off);
    }
    if (lane == 0) {
        float p[E_TOT];
        float mx = -1e30f;
#pragma unroll
        for (int e = 0; e < E_TOT; e++) { p[e] = dot[e] + gb[e]; mx = fmaxf(mx, p[e]); }
        float s = 0.f;
#pragma unroll
        for (int e = 0; e < E_TOT; e++) { p[e] = expf(p[e] - mx); s += p[e]; }
        int i1 = 0;
#pragma unroll
        for (int e = 1; e < E_TOT; e++) if (p[e] > p[i1]) i1 = e;
        int i2 = (i1 == 0) ? 1 : 0;
#pragma unroll
        for (int e = 0; e < E_TOT; e++) if (e != i1 && p[e] > p[i2]) i2 = e;

        float w1 = p[i1] / s, w2 = p[i2] / s;
        float t1 = (i1 < E_TRUE) ? w1 : 0.f;
        float t2 = (i2 < E_TRUE) ? w2 : 0.f;
        float den = t1 + t2;
        den = (den > 0.f) ? den : 1.f;
        t1 /= den; t2 /= den;
        if (i1 < E_TRUE) {
            int pos = atomicAdd(&g_cnt[i1], 1);
            g_tok[i1 * MAX_T + pos] = t;  g_wt[i1 * MAX_T + pos] = t1;
        }
        if (i2 < E_TRUE) {
            int pos = atomicAdd(&g_cnt[i2], 1);
            g_tok[i2 * MAX_T + pos] = t;  g_wt[i2 * MAX_T + pos] = t2;
        }
    }
}

// ew[e][k][n] fp32 -> transposed fp16 [e][n][k] x 1024.
// Also zeroes g_cnt (block 0; runs before gate_kernel by stream order).
__global__ __launch_bounds__(256)
void convert_w(const float* __restrict__ ew) {
    __shared__ float tile[64][65];
    const int e  = blockIdx.z;
    const int n0 = blockIdx.x * 64;
    const int k0 = blockIdx.y * 64;
    const int tid = threadIdx.x;
    const int seg = tid & 15;
    const int row = tid >> 4;

    if (blockIdx.x == 0 && blockIdx.y == 0 && blockIdx.z == 0 && tid < E_TRUE)
        g_cnt[tid] = 0;

    const float* src = ew + (size_t)e * D * D;
#pragma unroll
    for (int p = 0; p < 4; p++) {
        int k = row + p * 16;
        float4 v = *(const float4*)(src + (size_t)(k0 + k) * D + n0 + seg * 4);
        tile[k][seg * 4 + 0] = v.x;
        tile[k][seg * 4 + 1] = v.y;
        tile[k][seg * 4 + 2] = v.z;
        tile[k][seg * 4 + 3] = v.w;
    }
    __syncthreads();

    __half* dst = g_w + (size_t)e * D * D;
#pragma unroll
    for (int p = 0; p < 4; p++) {
        int n = row + p * 16;
        int kk = seg * 4;
        __half2 h01 = __floats2half2_rn(tile[kk + 0][n] * W_SCALE,
                                        tile[kk + 1][n] * W_SCALE);
        __half2 h23 = __floats2half2_rn(tile[kk + 2][n] * W_SCALE,
                                        tile[kk + 3][n] * W_SCALE);
        uint2 pk;
        pk.x = *(uint32_t*)&h01;
        pk.y = *(uint32_t*)&h23;
        *(uint2*)(dst + (size_t)(n0 + n) * D + k0 + kk) = pk;
    }
}

// ---------------------------------------------------------------------------
// Grouped fp16 HMMA GEMM (single pass). grid = (N/BN, maxMtiles, E_TRUE).
// Warp tile 64x32, mma.m16n8k16, fp32 accum, occ 2.
__global__ __launch_bounds__(256, 2)
void moe_mma(const float* __restrict__ eb, float* __restrict__ out) {
    extern __shared__ __align__(1024) char smem[];
    const int e = blockIdx.z;
    const int rows = g_cnt[e];
    const int m0 = blockIdx.y * BM;
    if (m0 >= rows) return;
    const int n0 = blockIdx.x * BN;

    const uint32_t sb = smem_u32(smem);
    const int tid = threadIdx.x;
    const int wid = tid >> 5;
    const int lane = tid & 31;
    const int wm = (wid >> 2) * 64;
    const int wn = (wid & 3) * 32;

    int*   sTok = (int*)(smem + OFF_TOK);
    float* sW   = (float*)(smem + OFF_W);
    if (tid < BM) {
        int gr = m0 + tid;
        sTok[tid] = (gr < rows) ? g_tok[e * MAX_T + gr] : 0;
        sW[tid]   = (gr < rows) ? g_wt [e * MAX_T + gr] : 0.f;
    }
    __syncthreads();

    const __half* wsrc = g_w + (size_t)e * D * D;

    int cRow[4], cGrp[4];
    uint32_t cSw[4];
#pragma unroll
    for (int t = 0; t < 4; t++) {
        int c = tid + t * 256;
        cRow[t] = c >> 3;
        cGrp[t] = c & 7;
        cSw[t]  = SW128((uint32_t)(cRow[t] * 128 + cGrp[t] * 16));
    }

    auto loadChunk = [&](int kc, int buf) {
        const int k0 = kc * KT;
        uint32_t abase = sb + OFF_A + buf * 16384;
        uint32_t bbase = sb + OFF_B + buf * 16384;
#pragma unroll
        for (int t = 0; t < 4; t++) {
            cp16(abase + cSw[t],
                 g_x + (size_t)sTok[cRow[t]] * D + k0 + cGrp[t] * 8);
            cp16(bbase + cSw[t],
                 wsrc + (size_t)(n0 + cRow[t]) * D + k0 + cGrp[t] * 8);
        }
        cp_commit();
    };

    uint32_t aOff[4], bOff[2];
#pragma unroll
    for (int i = 0; i < 4; i++)
        aOff[i] = (uint32_t)((wm + 16 * i + (lane & 15)) * 128 + (lane >> 4) * 16);
#pragma unroll
    for (int jj = 0; jj < 2; jj++)
        bOff[jj] = (uint32_t)((wn + 16 * jj + ((lane >> 3) & 1) * 8 + (lane & 7)) * 128
                              + (lane >> 4) * 16);

    float acc[4][4][4];
#pragma unroll
    for (int i = 0; i < 4; i++)
#pragma unroll
        for (int j = 0; j < 4; j++)
#pragma unroll
            for (int r = 0; r < 4; r++) acc[i][j][r] = 0.f;

    loadChunk(0, 0);

    for (int kc = 0; kc < NKC; kc++) {
        const int buf = kc & 1;
        if (kc + 1 < NKC) { loadChunk(kc + 1, buf ^ 1); cp_wait<1>(); }
        else              { cp_wait<0>(); }
        __syncthreads();

        const uint32_t ab = sb + OFF_A + buf * 16384;
        const uint32_t bb = sb + OFF_B + buf * 16384;

#pragma unroll
        for (int ks = 0; ks < 4; ks++) {
            uint32_t b[2][4];
#pragma unroll
            for (int jj = 0; jj < 2; jj++)
                ldsm_x4(b[jj], bb + SW128(bOff[jj] + ks * 32));
            uint32_t a[4][4];
#pragma unroll
            for (int i = 0; i < 4; i++)
                ldsm_x4(a[i], ab + SW128(aOff[i] + ks * 32));
#pragma unroll
            for (int i = 0; i < 4; i++)
#pragma unroll
                for (int j = 0; j < 4; j++)
                    mma16816(acc[i][j], a[i],
                             b[j >> 1][j & 1], b[j >> 1][(j & 1) + 2]);
        }
        __syncthreads();
    }

    // Epilogue: undo W_SCALE, add bias, apply gate weight, scatter-atomic.
    const int tig = lane & 3;
    const int grp = lane >> 2;
    const float* brow = eb + e * D + n0 + wn;
#pragma unroll
    for (int i = 0; i < 4; i++) {
#pragma unroll
        for (int h = 0; h < 2; h++) {
            int r = wm + 16 * i + grp + h * 8;
            int gr = m0 + r;
            if (gr < rows) {
                int tok = sTok[r];
                float w = sW[r];
                float* orow = out + (size_t)tok * D + n0 + wn;
#pragma unroll
                for (int j = 0; j < 4; j++) {
                    int col = 8 * j + 2 * tig;
                    float y0 = acc[i][j][h * 2 + 0] * W_INV_SCALE;
                    float y1 = acc[i][j][h * 2 + 1] * W_INV_SCALE;
                    atomicAdd(&orow[col],     w * (y0 + brow[col]));
                    atomicAdd(&orow[col + 1], w * (y1 + brow[col + 1]));
                }
            }
        }
    }
}

// ---------------------------------------------------------------------------
extern "C" void kernel_launch(void* const* d_in, const int* in_sizes, int n_in,
                              void* d_out, int out_size) {
    const float* x  = (const float*)d_in[0];
    const float* gw = (const float*)d_in[1];
    const float* gb = (const float*)d_in[2];
    const float* ew = (const float*)d_in[3];
    const float* eb = (const float*)d_in[4];
    float* out = (float*)d_out;

    const int T = in_sizes[0] / D;

    cudaFuncSetAttribute(moe_mma, cudaFuncAttributeMaxDynamicSharedMemorySize,
                         SMEM_BYTES);

    cudaMemsetAsync(out, 0, (size_t)out_size * sizeof(float), 0);

    {   // weight transpose + fp16 convert (also zeroes g_cnt)
        dim3 grid(D / 64, D / 64, E_TRUE);
        convert_w<<<grid, 256>>>(ew);
    }
    {   // fused gating + x fp16 convert
        int threads = 256;
        int blocks = (T * 32 + threads - 1) / threads;
        gate_kernel<<<blocks, threads>>>(x, gw, gb, T);
    }
    {   // grouped HMMA GEMM (single pass)
        dim3 grid(D / BN, (T + BM - 1) / BM, E_TRUE);
        moe_mma<<<grid, 256, SMEM_BYTES>>>(eb, out);
    }
}

// round 13
// speedup vs baseline: 4.7455x; 1.0044x over previous
#include <cuda_runtime.h>
#include <cuda_fp16.h>
#include <math.h>
#include <stdint.h>

#define D        1024
#define E_TOT    10
#define E_TRUE   8
#define MAX_T    8192
#define BM       128
#define BN       128
#define KT       64        // k-chunk: 64 fp16 = 128 bytes = one SW128 row
#define NKC      (D / KT)  // 16 chunks
#define W_SCALE      1024.0f
#define W_INV_SCALE  (1.0f / 1024.0f)

// ---------------- device scratch (__device__ globals) ----------------------
__device__ int   g_cnt[E_TRUE];
__device__ int   g_tok[E_TRUE * MAX_T];
__device__ float g_wt [E_TRUE * MAX_T];
__device__ __half g_x  [MAX_T * D];        // fp16(x)
__device__ __half g_w  [E_TRUE * D * D];   // [e][n][k] transposed, x1024

// ---------------- PTX helpers (<= sm_90 baseline features only) ------------
__device__ __forceinline__ uint32_t smem_u32(const void* p) {
    uint32_t a;
    asm("{ .reg .u64 t; cvta.to.shared.u64 t, %1; cvt.u32.u64 %0, t; }"
        : "=r"(a) : "l"(p));
    return a;
}
#define SW128(off) ((off) ^ (((off) >> 3) & 0x70))

__device__ __forceinline__ void cp16(uint32_t dst, const void* src) {
    asm volatile("cp.async.cg.shared.global [%0], [%1], 16;"
                 :: "r"(dst), "l"(__cvta_generic_to_global(src)));
}
__device__ __forceinline__ void cp_commit() {
    asm volatile("cp.async.commit_group;");
}
template <int N>
__device__ __forceinline__ void cp_wait() {
    asm volatile("cp.async.wait_group %0;" :: "n"(N));
}
__device__ __forceinline__ void ldsm_x4(uint32_t* r, uint32_t addr) {
    asm volatile("ldmatrix.sync.aligned.m8n8.x4.shared.b16 {%0,%1,%2,%3}, [%4];"
                 : "=r"(r[0]), "=r"(r[1]), "=r"(r[2]), "=r"(r[3]) : "r"(addr));
}
__device__ __forceinline__ void mma16816(float* d, const uint32_t* a,
                                         uint32_t b0, uint32_t b1) {
    asm volatile(
        "mma.sync.aligned.m16n8k16.row.col.f32.f16.f16.f32 "
        "{%0,%1,%2,%3}, {%4,%5,%6,%7}, {%8,%9}, {%0,%1,%2,%3};"
        : "+f"(d[0]), "+f"(d[1]), "+f"(d[2]), "+f"(d[3])
        : "r"(a[0]), "r"(a[1]), "r"(a[2]), "r"(a[3]), "r"(b0), "r"(b1));
}

// ---------------- SMEM layout ----------------------------------------------
#define OFF_TOK  0                   // 128 ints
#define OFF_W    512                 // 128 floats
#define OFF_A    1024                // A(buf): 2 x 16KB
#define OFF_B    (1024 + 2*16384)    // B(buf): 2 x 16KB
#define SMEM_BYTES (OFF_B + 2*16384) // 66560 -> 2 CTAs/SM

// ---------------------------------------------------------------------------
// Fused gating + fp16 conversion of x. One warp per token. Also zeroes g_cnt
// via the first block (grid-sync-free: block 0 does it BEFORE any other block
// can scatter? No -- ordering across blocks is not guaranteed, so g_cnt is
// zeroed by a preceding tiny kernel on the same stream instead).
__global__ void init_kernel() {
    if (threadIdx.x < E_TRUE) g_cnt[threadIdx.x] = 0;
}

__global__ void gate_kernel(const float* __restrict__ x,
                            const float* __restrict__ gw,
                            const float* __restrict__ gb, int T) {
    int gtid = blockIdx.x * blockDim.x + threadIdx.x;
    int t = gtid >> 5;
    int lane = gtid & 31;
    if (t >= T) return;
    const float4* xr  = (const float4*)(x + (size_t)t * D);
    const float4* gw4 = (const float4*)gw;

    float dot[E_TOT];
#pragma unroll
    for (int e = 0; e < E_TOT; e++) dot[e] = 0.f;

#pragma unroll
    for (int p = 0; p < 8; p++) {
        int f = p * 32 + lane;              // float4 index within row
        float4 v = xr[f];
        __half2 h01 = __floats2half2_rn(v.x, v.y);
        __half2 h23 = __floats2half2_rn(v.z, v.w);
        uint2 pk;
        pk.x = *(uint32_t*)&h01;
        pk.y = *(uint32_t*)&h23;
        *(uint2*)(g_x + (size_t)t * D + f * 4) = pk;
#pragma unroll
        for (int e = 0; e < E_TOT; e++) {
            float4 w = gw4[e * (D / 4) + f];
            dot[e] += v.x * w.x + v.y * w.y + v.z * w.z + v.w * w.w;
        }
    }
#pragma unroll
    for (int e = 0; e < E_TOT; e++) {
#pragma unroll
        for (int off = 16; off; off >>= 1)
            dot[e] += __shfl_xor_sync(0xffffffffu, dot[e], off);
    }
    if (lane == 0) {
        float p[E_TOT];
        float mx = -1e30f;
#pragma unroll
        for (int e = 0; e < E_TOT; e++) { p[e] = dot[e] + gb[e]; mx = fmaxf(mx, p[e]); }
        float s = 0.f;
#pragma unroll
        for (int e = 0; e < E_TOT; e++) { p[e] = expf(p[e] - mx); s += p[e]; }
        int i1 = 0;
#pragma unroll
        for (int e = 1; e < E_TOT; e++) if (p[e] > p[i1]) i1 = e;
        int i2 = (i1 == 0) ? 1 : 0;
#pragma unroll
        for (int e = 0; e < E_TOT; e++) if (e != i1 && p[e] > p[i2]) i2 = e;

        float w1 = p[i1] / s, w2 = p[i2] / s;
        float t1 = (i1 < E_TRUE) ? w1 : 0.f;
        float t2 = (i2 < E_TRUE) ? w2 : 0.f;
        float den = t1 + t2;
        den = (den > 0.f) ? den : 1.f;
        t1 /= den; t2 /= den;
        if (i1 < E_TRUE) {
            int pos = atomicAdd(&g_cnt[i1], 1);
            g_tok[i1 * MAX_T + pos] = t;  g_wt[i1 * MAX_T + pos] = t1;
        }
        if (i2 < E_TRUE) {
            int pos = atomicAdd(&g_cnt[i2], 1);
            g_tok[i2 * MAX_T + pos] = t;  g_wt[i2 * MAX_T + pos] = t2;
        }
    }
}

// ew[e][k][n] fp32 -> transposed fp16 [e][n][k] x 1024.
__global__ __launch_bounds__(256)
void convert_w(const float* __restrict__ ew) {
    __shared__ float tile[64][65];
    const int e  = blockIdx.z;
    const int n0 = blockIdx.x * 64;
    const int k0 = blockIdx.y * 64;
    const int tid = threadIdx.x;
    const int seg = tid & 15;
    const int row = tid >> 4;

    const float* src = ew + (size_t)e * D * D;
#pragma unroll
    for (int p = 0; p < 4; p++) {
        int k = row + p * 16;
        float4 v = *(const float4*)(src + (size_t)(k0 + k) * D + n0 + seg * 4);
        tile[k][seg * 4 + 0] = v.x;
        tile[k][seg * 4 + 1] = v.y;
        tile[k][seg * 4 + 2] = v.z;
        tile[k][seg * 4 + 3] = v.w;
    }
    __syncthreads();

    __half* dst = g_w + (size_t)e * D * D;
#pragma unroll
    for (int p = 0; p < 4; p++) {
        int n = row + p * 16;
        int kk = seg * 4;
        __half2 h01 = __floats2half2_rn(tile[kk + 0][n] * W_SCALE,
                                        tile[kk + 1][n] * W_SCALE);
        __half2 h23 = __floats2half2_rn(tile[kk + 2][n] * W_SCALE,
                                        tile[kk + 3][n] * W_SCALE);
        uint2 pk;
        pk.x = *(uint32_t*)&h01;
        pk.y = *(uint32_t*)&h23;
        *(uint2*)(dst + (size_t)(n0 + n) * D + k0 + kk) = pk;
    }
}

// ---------------------------------------------------------------------------
// Grouped fp16 HMMA GEMM (single pass). grid = (N/BN, maxMtiles, E_TRUE).
// Warp tile 64x32, mma.m16n8k16, fp32 accum, occ 2.
__global__ __launch_bounds__(256, 2)
void moe_mma(const float* __restrict__ eb, float* __restrict__ out) {
    extern __shared__ __align__(1024) char smem[];
    const int e = blockIdx.z;
    const int rows = g_cnt[e];
    const int m0 = blockIdx.y * BM;
    if (m0 >= rows) return;
    const int n0 = blockIdx.x * BN;

    const uint32_t sb = smem_u32(smem);
    const int tid = threadIdx.x;
    const int wid = tid >> 5;
    const int lane = tid & 31;
    const int wm = (wid >> 2) * 64;
    const int wn = (wid & 3) * 32;

    int*   sTok = (int*)(smem + OFF_TOK);
    float* sW   = (float*)(smem + OFF_W);
    if (tid < BM) {
        int gr = m0 + tid;
        sTok[tid] = (gr < rows) ? g_tok[e * MAX_T + gr] : 0;
        sW[tid]   = (gr < rows) ? g_wt [e * MAX_T + gr] : 0.f;
    }
    __syncthreads();

    const __half* wsrc = g_w + (size_t)e * D * D;

    int cRow[4], cGrp[4];
    uint32_t cSw[4];
#pragma unroll
    for (int t = 0; t < 4; t++) {
        int c = tid + t * 256;
        cRow[t] = c >> 3;
        cGrp[t] = c & 7;
        cSw[t]  = SW128((uint32_t)(cRow[t] * 128 + cGrp[t] * 16));
    }

    auto loadChunk = [&](int kc, int buf) {
        const int k0 = kc * KT;
        uint32_t abase = sb + OFF_A + buf * 16384;
        uint32_t bbase = sb + OFF_B + buf * 16384;
#pragma unroll
        for (int t = 0; t < 4; t++) {
            cp16(abase + cSw[t],
                 g_x + (size_t)sTok[cRow[t]] * D + k0 + cGrp[t] * 8);
            cp16(bbase + cSw[t],
                 wsrc + (size_t)(n0 + cRow[t]) * D + k0 + cGrp[t] * 8);
        }
        cp_commit();
    };

    uint32_t aOff[4], bOff[2];
#pragma unroll
    for (int i = 0; i < 4; i++)
        aOff[i] = (uint32_t)((wm + 16 * i + (lane & 15)) * 128 + (lane >> 4) * 16);
#pragma unroll
    for (int jj = 0; jj < 2; jj++)
        bOff[jj] = (uint32_t)((wn + 16 * jj + ((lane >> 3) & 1) * 8 + (lane & 7)) * 128
                              + (lane >> 4) * 16);

    float acc[4][4][4];
#pragma unroll
    for (int i = 0; i < 4; i++)
#pragma unroll
        for (int j = 0; j < 4; j++)
#pragma unroll
            for (int r = 0; r < 4; r++) acc[i][j][r] = 0.f;

    loadChunk(0, 0);

    for (int kc = 0; kc < NKC; kc++) {
        const int buf = kc & 1;
        if (kc + 1 < NKC) { loadChunk(kc + 1, buf ^ 1); cp_wait<1>(); }
        else              { cp_wait<0>(); }
        __syncthreads();

        const uint32_t ab = sb + OFF_A + buf * 16384;
        const uint32_t bb = sb + OFF_B + buf * 16384;

#pragma unroll
        for (int ks = 0; ks < 4; ks++) {
            uint32_t b[2][4];
#pragma unroll
            for (int jj = 0; jj < 2; jj++)
                ldsm_x4(b[jj], bb + SW128(bOff[jj] + ks * 32));
            uint32_t a[4][4];
#pragma unroll
            for (int i = 0; i < 4; i++)
                ldsm_x4(a[i], ab + SW128(aOff[i] + ks * 32));
#pragma unroll
            for (int i = 0; i < 4; i++)
#pragma unroll
                for (int j = 0; j < 4; j++)
                    mma16816(acc[i][j], a[i],
                             b[j >> 1][j & 1], b[j >> 1][(j & 1) + 2]);
        }
        __syncthreads();
    }

    // Epilogue: undo W_SCALE, add bias, apply gate weight, scatter-atomic.
    const int tig = lane & 3;
    const int grp = lane >> 2;
    const float* brow = eb + e * D + n0 + wn;
#pragma unroll
    for (int i = 0; i < 4; i++) {
#pragma unroll
        for (int h = 0; h < 2; h++) {
            int r = wm + 16 * i + grp + h * 8;
            int gr = m0 + r;
            if (gr < rows) {
                int tok = sTok[r];
                float w = sW[r];
                float* orow = out + (size_t)tok * D + n0 + wn;
#pragma unroll
                for (int j = 0; j < 4; j++) {
                    int col = 8 * j + 2 * tig;
                    float y0 = acc[i][j][h * 2 + 0] * W_INV_SCALE;
                    float y1 = acc[i][j][h * 2 + 1] * W_INV_SCALE;
                    atomicAdd(&orow[col],     w * (y0 + brow[col]));
                    atomicAdd(&orow[col + 1], w * (y1 + brow[col + 1]));
                }
            }
        }
    }
}

// ---------------------------------------------------------------------------
// Side streams/events: created once (lazy static init); no device memory is
// allocated. Work per call is identical and deterministic.
static cudaStream_t s_w = nullptr, s_m = nullptr;
static cudaEvent_t  ev_fork_w = nullptr, ev_fork_m = nullptr;
static cudaEvent_t  ev_join_w = nullptr, ev_join_m = nullptr;

extern "C" void kernel_launch(void* const* d_in, const int* in_sizes, int n_in,
                              void* d_out, int out_size) {
    const float* x  = (const float*)d_in[0];
    const float* gw = (const float*)d_in[1];
    const float* gb = (const float*)d_in[2];
    const float* ew = (const float*)d_in[3];
    const float* eb = (const float*)d_in[4];
    float* out = (float*)d_out;

    const int T = in_sizes[0] / D;

    if (!s_w) {
        cudaStreamCreateWithFlags(&s_w, cudaStreamNonBlocking);
        cudaStreamCreateWithFlags(&s_m, cudaStreamNonBlocking);
        cudaEventCreateWithFlags(&ev_fork_w, cudaEventDisableTiming);
        cudaEventCreateWithFlags(&ev_fork_m, cudaEventDisableTiming);
        cudaEventCreateWithFlags(&ev_join_w, cudaEventDisableTiming);
        cudaEventCreateWithFlags(&ev_join_m, cudaEventDisableTiming);
        cudaFuncSetAttribute(moe_mma,
                             cudaFuncAttributeMaxDynamicSharedMemorySize,
                             SMEM_BYTES);
    }

    cudaStream_t s0 = 0;   // capture (legacy default) stream

    // fork
    cudaEventRecord(ev_fork_w, s0);
    cudaEventRecord(ev_fork_m, s0);
    cudaStreamWaitEvent(s_w, ev_fork_w, 0);
    cudaStreamWaitEvent(s_m, ev_fork_m, 0);

    // branch W: weight transpose + fp16 convert
    {
        dim3 grid(D / 64, D / 64, E_TRUE);
        convert_w<<<grid, 256, 0, s_w>>>(ew);
        cudaEventRecord(ev_join_w, s_w);
    }
    // branch M: zero the output
    {
        cudaMemsetAsync(out, 0, (size_t)out_size * sizeof(float), s_m);
        cudaEventRecord(ev_join_m, s_m);
    }
    // main stream: routing init + fused gating / x conversion
    {
        init_kernel<<<1, 32, 0, s0>>>();
        int threads = 256;
        int blocks = (T * 32 + threads - 1) / threads;
        gate_kernel<<<blocks, threads, 0, s0>>>(x, gw, gb, T);
    }

    // join
    cudaStreamWaitEvent(s0, ev_join_w, 0);
    cudaStreamWaitEvent(s0, ev_join_m, 0);

    // grouped HMMA GEMM (single pass)
    {
        dim3 grid(D / BN, (T + BM - 1) / BM, E_TRUE);
        moe_mma<<<grid, 256, SMEM_BYTES, s0>>>(eb, out);
    }
}

// round 14
// speedup vs baseline: 4.9459x; 1.0422x over previous
#include <cuda_runtime.h>
#include <cuda_fp16.h>
#include <math.h>
#include <stdint.h>

#define D        1024
#define E_TOT    10
#define E_TRUE   8
#define MAX_T    8192
#define BM       128
#define BN       128
#define KT       64        // k-chunk: 64 fp16 = 128 bytes = one SW128 row
#define NKC      (D / KT)  // 16 chunks
#define STAGES   3
#define W_SCALE      1024.0f
#define W_INV_SCALE  (1.0f / 1024.0f)

// ---------------- device scratch (__device__ globals) ----------------------
__device__ int   g_cnt[E_TRUE];
__device__ int   g_tok[E_TRUE * MAX_T];
__device__ float g_wt [E_TRUE * MAX_T];
__device__ __half g_x  [MAX_T * D];        // fp16(x)
__device__ __half g_w  [E_TRUE * D * D];   // [e][n][k] transposed, x1024

// ---------------- PTX helpers (<= sm_90 baseline features only) ------------
__device__ __forceinline__ uint32_t smem_u32(const void* p) {
    uint32_t a;
    asm("{ .reg .u64 t; cvta.to.shared.u64 t, %1; cvt.u32.u64 %0, t; }"
        : "=r"(a) : "l"(p));
    return a;
}
#define SW128(off) ((off) ^ (((off) >> 3) & 0x70))

__device__ __forceinline__ void cp16(uint32_t dst, const void* src) {
    asm volatile("cp.async.cg.shared.global [%0], [%1], 16;"
                 :: "r"(dst), "l"(__cvta_generic_to_global(src)));
}
__device__ __forceinline__ void cp_commit() {
    asm volatile("cp.async.commit_group;");
}
template <int N>
__device__ __forceinline__ void cp_wait() {
    asm volatile("cp.async.wait_group %0;" :: "n"(N));
}
__device__ __forceinline__ void ldsm_x4(uint32_t* r, uint32_t addr) {
    asm volatile("ldmatrix.sync.aligned.m8n8.x4.shared.b16 {%0,%1,%2,%3}, [%4];"
                 : "=r"(r[0]), "=r"(r[1]), "=r"(r[2]), "=r"(r[3]) : "r"(addr));
}
__device__ __forceinline__ void mma16816(float* d, const uint32_t* a,
                                         uint32_t b0, uint32_t b1) {
    asm volatile(
        "mma.sync.aligned.m16n8k16.row.col.f32.f16.f16.f32 "
        "{%0,%1,%2,%3}, {%4,%5,%6,%7}, {%8,%9}, {%0,%1,%2,%3};"
        : "+f"(d[0]), "+f"(d[1]), "+f"(d[2]), "+f"(d[3])
        : "r"(a[0]), "r"(a[1]), "r"(a[2]), "r"(a[3]), "r"(b0), "r"(b1));
}

// ---------------- moe_mma SMEM layout (3-stage) -----------------------------
#define OFF_TOK  0                        // 128 ints
#define OFF_W    512                      // 128 floats
#define OFF_A    1024                     // A stages: 3 x 16KB
#define OFF_B    (1024 + STAGES*16384)    // B stages: 3 x 16KB
#define SMEM_BYTES (OFF_B + STAGES*16384) // 99328 -> 2 CTAs/SM

#define GATE_BLOCKS  (MAX_T / 8)          // 1024 (8 tokens per 256-thr block)
#define CONVW_BLOCKS (E_TRUE * 16 * 16)   // 2048 (64x64 tiles)

// ---------------------------------------------------------------------------
__global__ void init_kernel() {
    if (threadIdx.x < E_TRUE) g_cnt[threadIdx.x] = 0;
}

// Fused prologue: blocks [0, GATE_BLOCKS) do gating + x fp16 convert + zero
// the token's output row; blocks [GATE_BLOCKS, +CONVW_BLOCKS) transpose and
// convert one 64x64 weight tile.
__global__ __launch_bounds__(256)
void prologue_kernel(const float* __restrict__ x,
                     const float* __restrict__ gw,
                     const float* __restrict__ gb,
                     const float* __restrict__ ew,
                     float* __restrict__ out, int T) {
    const int tid = threadIdx.x;

    if (blockIdx.x < GATE_BLOCKS) {
        // ---------------- gate + convert_x + zero out rows ----------------
        int gtid = blockIdx.x * 256 + tid;
        int t = gtid >> 5;
        int lane = gtid & 31;
        if (t >= T) return;

        // zero this token's output row (32 float4 per warp, 8 per lane... )
        {
            float4 z = make_float4(0.f, 0.f, 0.f, 0.f);
            float4* orow = (float4*)(out + (size_t)t * D);
#pragma unroll
            for (int p = 0; p < 8; p++) orow[p * 32 + lane] = z;
        }

        const float4* xr  = (const float4*)(x + (size_t)t * D);
        const float4* gw4 = (const float4*)gw;

        float dot[E_TOT];
#pragma unroll
        for (int e = 0; e < E_TOT; e++) dot[e] = 0.f;

#pragma unroll
        for (int p = 0; p < 8; p++) {
            int f = p * 32 + lane;
            float4 v = xr[f];
            __half2 h01 = __floats2half2_rn(v.x, v.y);
            __half2 h23 = __floats2half2_rn(v.z, v.w);
            uint2 pk;
            pk.x = *(uint32_t*)&h01;
            pk.y = *(uint32_t*)&h23;
            *(uint2*)(g_x + (size_t)t * D + f * 4) = pk;
#pragma unroll
            for (int e = 0; e < E_TOT; e++) {
                float4 w = gw4[e * (D / 4) + f];
                dot[e] += v.x * w.x + v.y * w.y + v.z * w.z + v.w * w.w;
            }
        }
#pragma unroll
        for (int e = 0; e < E_TOT; e++) {
#pragma unroll
            for (int off = 16; off; off >>= 1)
                dot[e] += __shfl_xor_sync(0xffffffffu, dot[e], off);
        }
        if (lane == 0) {
            float p[E_TOT];
            float mx = -1e30f;
#pragma unroll
            for (int e = 0; e < E_TOT; e++) { p[e] = dot[e] + gb[e]; mx = fmaxf(mx, p[e]); }
            float s = 0.f;
#pragma unroll
            for (int e = 0; e < E_TOT; e++) { p[e] = expf(p[e] - mx); s += p[e]; }
            int i1 = 0;
#pragma unroll
            for (int e = 1; e < E_TOT; e++) if (p[e] > p[i1]) i1 = e;
            int i2 = (i1 == 0) ? 1 : 0;
#pragma unroll
            for (int e = 0; e < E_TOT; e++) if (e != i1 && p[e] > p[i2]) i2 = e;

            float w1 = p[i1] / s, w2 = p[i2] / s;
            float t1 = (i1 < E_TRUE) ? w1 : 0.f;
            float t2 = (i2 < E_TRUE) ? w2 : 0.f;
            float den = t1 + t2;
            den = (den > 0.f) ? den : 1.f;
            t1 /= den; t2 /= den;
            if (i1 < E_TRUE) {
                int pos = atomicAdd(&g_cnt[i1], 1);
                g_tok[i1 * MAX_T + pos] = t;  g_wt[i1 * MAX_T + pos] = t1;
            }
            if (i2 < E_TRUE) {
                int pos = atomicAdd(&g_cnt[i2], 1);
                g_tok[i2 * MAX_T + pos] = t;  g_wt[i2 * MAX_T + pos] = t2;
            }
        }
    } else {
        // ---------------- convert_w: one 64x64 tile ------------------------
        __shared__ float tile[64][65];
        int idx = blockIdx.x - GATE_BLOCKS;       // 0..2047
        const int e  = idx >> 8;                  // /256
        const int n0 = (idx & 15) * 64;
        const int k0 = ((idx >> 4) & 15) * 64;
        const int seg = tid & 15;
        const int row = tid >> 4;

        const float* src = ew + (size_t)e * D * D;
#pragma unroll
        for (int p = 0; p < 4; p++) {
            int k = row + p * 16;
            float4 v = *(const float4*)(src + (size_t)(k0 + k) * D + n0 + seg * 4);
            tile[k][seg * 4 + 0] = v.x;
            tile[k][seg * 4 + 1] = v.y;
            tile[k][seg * 4 + 2] = v.z;
            tile[k][seg * 4 + 3] = v.w;
        }
        __syncthreads();

        __half* dst = g_w + (size_t)e * D * D;
#pragma unroll
        for (int p = 0; p < 4; p++) {
            int n = row + p * 16;
            int kk = seg * 4;
            __half2 h01 = __floats2half2_rn(tile[kk + 0][n] * W_SCALE,
                                            tile[kk + 1][n] * W_SCALE);
            __half2 h23 = __floats2half2_rn(tile[kk + 2][n] * W_SCALE,
                                            tile[kk + 3][n] * W_SCALE);
            uint2 pk;
            pk.x = *(uint32_t*)&h01;
            pk.y = *(uint32_t*)&h23;
            *(uint2*)(dst + (size_t)(n0 + n) * D + k0 + kk) = pk;
        }
    }
}

// ---------------------------------------------------------------------------
// Grouped fp16 HMMA GEMM, 3-stage cp.async pipeline, one barrier per chunk.
// grid = (N/BN, maxMtiles, E_TRUE), 256 thr, warp tile 64x32, occ 2.
__global__ __launch_bounds__(256, 2)
void moe_mma(const float* __restrict__ eb, float* __restrict__ out) {
    extern __shared__ __align__(1024) char smem[];
    const int e = blockIdx.z;
    const int rows = g_cnt[e];
    const int m0 = blockIdx.y * BM;
    if (m0 >= rows) return;
    const int n0 = blockIdx.x * BN;

    const uint32_t sb = smem_u32(smem);
    const int tid = threadIdx.x;
    const int wid = tid >> 5;
    const int lane = tid & 31;
    const int wm = (wid >> 2) * 64;
    const int wn = (wid & 3) * 32;

    int*   sTok = (int*)(smem + OFF_TOK);
    float* sW   = (float*)(smem + OFF_W);
    if (tid < BM) {
        int gr = m0 + tid;
        sTok[tid] = (gr < rows) ? g_tok[e * MAX_T + gr] : 0;
        sW[tid]   = (gr < rows) ? g_wt [e * MAX_T + gr] : 0.f;
    }
    __syncthreads();

    const __half* wsrc = g_w + (size_t)e * D * D;

    int cRow[4], cGrp[4];
    uint32_t cSw[4];
#pragma unroll
    for (int t = 0; t < 4; t++) {
        int c = tid + t * 256;
        cRow[t] = c >> 3;
        cGrp[t] = c & 7;
        cSw[t]  = SW128((uint32_t)(cRow[t] * 128 + cGrp[t] * 16));
    }

    auto loadChunk = [&](int kc, int buf) {
        const int k0 = kc * KT;
        uint32_t abase = sb + OFF_A + buf * 16384;
        uint32_t bbase = sb + OFF_B + buf * 16384;
#pragma unroll
        for (int t = 0; t < 4; t++) {
            cp16(abase + cSw[t],
                 g_x + (size_t)sTok[cRow[t]] * D + k0 + cGrp[t] * 8);
            cp16(bbase + cSw[t],
                 wsrc + (size_t)(n0 + cRow[t]) * D + k0 + cGrp[t] * 8);
        }
        cp_commit();
    };

    uint32_t aOff[4], bOff[2];
#pragma unroll
    for (int i = 0; i < 4; i++)
        aOff[i] = (uint32_t)((wm + 16 * i + (lane & 15)) * 128 + (lane >> 4) * 16);
#pragma unroll
    for (int jj = 0; jj < 2; jj++)
        bOff[jj] = (uint32_t)((wn + 16 * jj + ((lane >> 3) & 1) * 8 + (lane & 7)) * 128
                              + (lane >> 4) * 16);

    float acc[4][4][4];
#pragma unroll
    for (int i = 0; i < 4; i++)
#pragma unroll
        for (int j = 0; j < 4; j++)
#pragma unroll
            for (int r = 0; r < 4; r++) acc[i][j][r] = 0.f;

    // prime STAGES-1 chunks
    loadChunk(0, 0);
    loadChunk(1, 1);

    for (int kc = 0; kc < NKC; kc++) {
        const int buf = kc % STAGES;
        cp_wait<STAGES - 2>();      // chunk kc resident
        __syncthreads();            // all warps done with buf (kc-1 compute) + see kc

        if (kc + STAGES - 1 < NKC)
            loadChunk(kc + STAGES - 1, (kc + STAGES - 1) % STAGES);

        const uint32_t ab = sb + OFF_A + buf * 16384;
        const uint32_t bb = sb + OFF_B + buf * 16384;

#pragma unroll
        for (int ks = 0; ks < 4; ks++) {
            uint32_t b[2][4];
#pragma unroll
            for (int jj = 0; jj < 2; jj++)
                ldsm_x4(b[jj], bb + SW128(bOff[jj] + ks * 32));
            uint32_t a[4][4];
#pragma unroll
            for (int i = 0; i < 4; i++)
                ldsm_x4(a[i], ab + SW128(aOff[i] + ks * 32));
#pragma unroll
            for (int i = 0; i < 4; i++)
#pragma unroll
                for (int j = 0; j < 4; j++)
                    mma16816(acc[i][j], a[i],
                             b[j >> 1][j & 1], b[j >> 1][(j & 1) + 2]);
        }
    }

    // Epilogue: undo W_SCALE, add bias, apply gate weight, scatter-atomic.
    const int tig = lane & 3;
    const int grp = lane >> 2;
    const float* brow = eb + e * D + n0 + wn;
#pragma unroll
    for (int i = 0; i < 4; i++) {
#pragma unroll
        for (int h = 0; h < 2; h++) {
            int r = wm + 16 * i + grp + h * 8;
            int gr = m0 + r;
            if (gr < rows) {
                int tok = sTok[r];
                float w = sW[r];
                float* orow = out + (size_t)tok * D + n0 + wn;
#pragma unroll
                for (int j = 0; j < 4; j++) {
                    int col = 8 * j + 2 * tig;
                    float y0 = acc[i][j][h * 2 + 0] * W_INV_SCALE;
                    float y1 = acc[i][j][h * 2 + 1] * W_INV_SCALE;
                    atomicAdd(&orow[col],     w * (y0 + brow[col]));
                    atomicAdd(&orow[col + 1], w * (y1 + brow[col + 1]));
                }
            }
        }
    }
}

// ---------------------------------------------------------------------------
extern "C" void kernel_launch(void* const* d_in, const int* in_sizes, int n_in,
                              void* d_out, int out_size) {
    const float* x  = (const float*)d_in[0];
    const float* gw = (const float*)d_in[1];
    const float* gb = (const float*)d_in[2];
    const float* ew = (const float*)d_in[3];
    const float* eb = (const float*)d_in[4];
    float* out = (float*)d_out;

    const int T = in_sizes[0] / D;

    static bool attr_set = false;
    if (!attr_set) {
        cudaFuncSetAttribute(moe_mma,
                             cudaFuncAttributeMaxDynamicSharedMemorySize,
                             SMEM_BYTES);
        attr_set = true;
    }

    init_kernel<<<1, 32>>>();

    {   // fused: gate + convert_x + zero-out + convert_w (one launch)
        prologue_kernel<<<GATE_BLOCKS + CONVW_BLOCKS, 256>>>(x, gw, gb, ew,
                                                             out, T);
    }
    {   // grouped HMMA GEMM (single pass, 3-stage pipeline)
        dim3 grid(D / BN, (T + BM - 1) / BM, E_TRUE);
        moe_mma<<<grid, 256, SMEM_BYTES>>>(eb, out);
    }
}